// round 8
// baseline (speedup 1.0000x reference)
#include <cuda_runtime.h>
#include <cuda_fp16.h>

#define N_NODES 50000
#define N_EDGES 1600000
#define IN_DIM 6
#define H 64
#define SCAN_BLOCKS ((N_NODES + 255) / 256)   // 196

// Scratch (device globals — zero-initialized at load; no runtime allocation)
__device__ int    g_deg     [N_NODES];        // reset to 0 by k_scan23 each replay
__device__ int    g_rowstart[N_NODES + 1];
__device__ int    g_pos     [N_EDGES];
__device__ int    g_adj     [N_EDGES];
__device__ int    g_bsum    [SCAN_BLOCKS];
__device__ float  g_mean1   [N_NODES * IN_DIM];
__device__ __half g_uh      [N_NODES * H];    // u = z @ W2_l   (fp16, gather operand)
__device__ float  g_yr      [N_NODES * H];    // yr = z @ W2_r + b2_l

// ---- CSR build ----------------------------------------------------------

// 4 edges per thread: vector loads, 4 independent atomic chains
__global__ void k_count(const int* __restrict__ ei) {
    int tid = blockIdx.x * blockDim.x + threadIdx.x;   // N_EDGES/4 threads
    if (tid >= N_EDGES / 4) return;
    const int4* dsts = reinterpret_cast<const int4*>(ei + N_EDGES);
    int4 d = __ldg(&dsts[tid]);
    int p0 = atomicAdd(&g_deg[d.x], 1);
    int p1 = atomicAdd(&g_deg[d.y], 1);
    int p2 = atomicAdd(&g_deg[d.z], 1);
    int p3 = atomicAdd(&g_deg[d.w], 1);
    reinterpret_cast<int4*>(g_pos)[tid] = make_int4(p0, p1, p2, p3);
}

__device__ __forceinline__ int warp_incl_scan(int v, int lane) {
    #pragma unroll
    for (int o = 1; o < 32; o <<= 1) {
        int u = __shfl_up_sync(0xffffffffu, v, o);
        if (lane >= o) v += u;
    }
    return v;
}

// Phase 1: per-block exclusive scan of g_deg -> partial rowstart + block sums
__global__ void k_scan1() {
    __shared__ int ws[8];
    int t = threadIdx.x;
    int i = blockIdx.x * 256 + t;
    int val = (i < N_NODES) ? g_deg[i] : 0;
    int lane = t & 31, w = t >> 5;
    int v = warp_incl_scan(val, lane);
    if (lane == 31) ws[w] = v;
    __syncthreads();
    if (w == 0 && lane < 8) {
        int u = ws[lane];
        #pragma unroll
        for (int o = 1; o < 8; o <<= 1) {
            int p = __shfl_up_sync(0xffu, u, o);
            if (lane >= o) u += p;
        }
        ws[lane] = u;
    }
    __syncthreads();
    int excl = (v - val) + (w > 0 ? ws[w - 1] : 0);
    if (i < N_NODES) g_rowstart[i] = excl;
    if (t == 255) g_bsum[blockIdx.x] = excl + val;
}

// Phase 2+3 merged: every block rescans the 196 block sums locally, derives
// its own offset, applies it, re-arms g_deg, closes the row pointer.
__global__ void k_scan23() {
    __shared__ int ws[8];
    __shared__ int incl[256];
    int t = threadIdx.x;
    int val = (t < SCAN_BLOCKS) ? g_bsum[t] : 0;
    int lane = t & 31, w = t >> 5;
    int v = warp_incl_scan(val, lane);
    if (lane == 31) ws[w] = v;
    __syncthreads();
    if (w == 0 && lane < 8) {
        int u = ws[lane];
        #pragma unroll
        for (int o = 1; o < 8; o <<= 1) {
            int p = __shfl_up_sync(0xffu, u, o);
            if (lane >= o) u += p;
        }
        ws[lane] = u;
    }
    __syncthreads();
    incl[t] = v + (w > 0 ? ws[w - 1] : 0);
    __syncthreads();
    int bid = blockIdx.x;
    int off = (bid > 0) ? incl[bid - 1] : 0;
    int i = bid * 256 + t;
    if (i < N_NODES) {
        g_rowstart[i] += off;
        g_deg[i] = 0;
    }
    if (i == 0) g_rowstart[N_NODES] = N_EDGES;
}

// Atomic-free placement, 4 edges per thread
__global__ void k_place(const int* __restrict__ ei) {
    int tid = blockIdx.x * blockDim.x + threadIdx.x;   // N_EDGES/4 threads
    if (tid >= N_EDGES / 4) return;
    const int4* srcs = reinterpret_cast<const int4*>(ei);
    const int4* dsts = reinterpret_cast<const int4*>(ei + N_EDGES);
    int4 s = __ldg(&srcs[tid]);
    int4 d = __ldg(&dsts[tid]);
    int4 p = reinterpret_cast<const int4*>(g_pos)[tid];
    int r0 = __ldg(&g_rowstart[d.x]);
    int r1 = __ldg(&g_rowstart[d.y]);
    int r2 = __ldg(&g_rowstart[d.z]);
    int r3 = __ldg(&g_rowstart[d.w]);
    g_adj[r0 + p.x] = s.x;
    g_adj[r1 + p.y] = s.y;
    g_adj[r2 + p.z] = s.z;
    g_adj[r3 + p.w] = s.w;
}

// ---- Layer 1 aggregation --------------------------------------------------

__global__ void k_agg1(const float* __restrict__ x) {
    int node = blockIdx.x * blockDim.x + threadIdx.x;
    if (node >= N_NODES) return;
    int beg = g_rowstart[node], end = g_rowstart[node + 1];
    float a0 = 0, a1 = 0, a2 = 0, a3 = 0, a4 = 0, a5 = 0;
    #pragma unroll 4
    for (int i = beg; i < end; i++) {
        int s = __ldg(&g_adj[i]);
        const float2* xs = reinterpret_cast<const float2*>(x + (size_t)s * IN_DIM);
        float2 p = __ldg(&xs[0]), q = __ldg(&xs[1]), r = __ldg(&xs[2]);
        a0 += p.x; a1 += p.y; a2 += q.x; a3 += q.y; a4 += r.x; a5 += r.y;
    }
    float inv = (end > beg) ? 1.0f / (float)(end - beg) : 0.0f;
    float* m = g_mean1 + (size_t)node * IN_DIM;
    m[0] = a0 * inv; m[1] = a1 * inv; m[2] = a2 * inv;
    m[3] = a3 * inv; m[4] = a4 * inv; m[5] = a5 * inv;
}

// ---- Fused node kernel: z = relu(L1), then u = z@W2_l (fp16), yr = z@W2_r + b2_l
__global__ void k_node(const float* __restrict__ x,
                       const float* __restrict__ W1l,
                       const float* __restrict__ b1l,
                       const float* __restrict__ W1r,
                       const float* __restrict__ W2l,
                       const float* __restrict__ b2l,
                       const float* __restrict__ W2r) {
    __shared__ float sW1l[IN_DIM * H];
    __shared__ float sW1r[IN_DIM * H];
    __shared__ float sb1[H];
    __shared__ float sW2l[H * H];
    __shared__ float sW2r[H * H];
    __shared__ float sb2[H];
    __shared__ float sz[32 * H];
    int t = threadIdx.x;
    for (int i = t; i < IN_DIM * H; i += 256) { sW1l[i] = W1l[i]; sW1r[i] = W1r[i]; }
    for (int i = t; i < H * H; i += 256)      { sW2l[i] = W2l[i]; sW2r[i] = W2r[i]; }
    if (t < H) { sb1[t] = b1l[t]; sb2[t] = b2l[t]; }
    __syncthreads();

    int base = blockIdx.x * 32;
    int local = t >> 6;
    int j = t & 63;
    #pragma unroll
    for (int g = 0; g < 8; g++) {
        int node = base + g * 4 + local;
        int ln = g * 4 + local;
        float zv = 0.0f;
        if (node < N_NODES) {
            float acc = sb1[j];
            #pragma unroll
            for (int k = 0; k < IN_DIM; k++) {
                acc += g_mean1[node * IN_DIM + k] * sW1l[k * H + j]
                     + x[node * IN_DIM + k]       * sW1r[k * H + j];
            }
            zv = fmaxf(acc, 0.0f);
        }
        sz[ln * H + j] = zv;
    }
    __syncthreads();
    for (int g = 0; g < 8; g++) {
        int node = base + g * 4 + local;
        if (node < N_NODES) {
            int ln = g * 4 + local;
            float au = 0.0f, ar = sb2[j];
            #pragma unroll 8
            for (int k = 0; k < H; k++) {
                float zv = sz[ln * H + k];
                au += zv * sW2l[k * H + j];
                ar += zv * sW2r[k * H + j];
            }
            g_uh[node * H + j] = __float2half(au);
            g_yr[node * H + j] = ar;
        }
    }
}

// ---- Layer 2 aggregation, fused epilogue: out = mean(u[nbrs]) + yr ---------

__device__ __forceinline__ void acc4(uint2 u, float& a0, float& a1, float& a2, float& a3) {
    __half2 hx = *reinterpret_cast<__half2*>(&u.x);
    __half2 hy = *reinterpret_cast<__half2*>(&u.y);
    float2 fx = __half22float2(hx);
    float2 fy = __half22float2(hy);
    a0 += fx.x; a1 += fx.y; a2 += fy.x; a3 += fy.y;
}

__global__ void k_agg2(float* __restrict__ out) {
    __shared__ float4 red[2][4][16];  // 2 nodes x 4 warps x 64 dims (as float4)
    int t = threadIdx.x;              // 256 = 2 nodes x 4 warps
    int grp  = t >> 7;
    int t128 = t & 127;
    int wg   = t128 >> 5;
    int lane = t & 31;
    int half = lane >> 4;             // which neighbor of the pair
    int sub  = lane & 15;             // dim group [sub*4, sub*4+4)
    int node = blockIdx.x * 2 + grp;  // N_NODES even: always valid

    int beg = g_rowstart[node];
    int end = g_rowstart[node + 1];
    int deg = end - beg;
    int chunk = (deg + 3) >> 2;
    int wbeg = beg + wg * chunk;
    int wend = wbeg + chunk; if (wend > end) wend = end;

    float a0 = 0, a1 = 0, a2 = 0, a3 = 0;
    const uint2* uh = reinterpret_cast<const uint2*>(g_uh);
    for (int base = wbeg; base < wend; base += 32) {
        int idx = base + lane;
        int sidx = (idx < wend) ? __ldg(&g_adj[idx]) : 0;
        int m = wend - base; if (m > 32) m = 32;
        int j = 0;
        // 16 neighbors per iter -> 8 independent 8B loads in flight per thread
        for (; j + 16 <= m; j += 16) {
            int p0 = __shfl_sync(0xffffffffu, sidx, j + 0  + half);
            int p1 = __shfl_sync(0xffffffffu, sidx, j + 2  + half);
            int p2 = __shfl_sync(0xffffffffu, sidx, j + 4  + half);
            int p3 = __shfl_sync(0xffffffffu, sidx, j + 6  + half);
            int p4 = __shfl_sync(0xffffffffu, sidx, j + 8  + half);
            int p5 = __shfl_sync(0xffffffffu, sidx, j + 10 + half);
            int p6 = __shfl_sync(0xffffffffu, sidx, j + 12 + half);
            int p7 = __shfl_sync(0xffffffffu, sidx, j + 14 + half);
            uint2 u0 = __ldg(&uh[(size_t)p0 * 16 + sub]);
            uint2 u1 = __ldg(&uh[(size_t)p1 * 16 + sub]);
            uint2 u2 = __ldg(&uh[(size_t)p2 * 16 + sub]);
            uint2 u3 = __ldg(&uh[(size_t)p3 * 16 + sub]);
            uint2 u4 = __ldg(&uh[(size_t)p4 * 16 + sub]);
            uint2 u5 = __ldg(&uh[(size_t)p5 * 16 + sub]);
            uint2 u6 = __ldg(&uh[(size_t)p6 * 16 + sub]);
            uint2 u7 = __ldg(&uh[(size_t)p7 * 16 + sub]);
            acc4(u0, a0, a1, a2, a3); acc4(u1, a0, a1, a2, a3);
            acc4(u2, a0, a1, a2, a3); acc4(u3, a0, a1, a2, a3);
            acc4(u4, a0, a1, a2, a3); acc4(u5, a0, a1, a2, a3);
            acc4(u6, a0, a1, a2, a3); acc4(u7, a0, a1, a2, a3);
        }
        for (; j + 8 <= m; j += 8) {
            int p0 = __shfl_sync(0xffffffffu, sidx, j + 0 + half);
            int p1 = __shfl_sync(0xffffffffu, sidx, j + 2 + half);
            int p2 = __shfl_sync(0xffffffffu, sidx, j + 4 + half);
            int p3 = __shfl_sync(0xffffffffu, sidx, j + 6 + half);
            uint2 u0 = __ldg(&uh[(size_t)p0 * 16 + sub]);
            uint2 u1 = __ldg(&uh[(size_t)p1 * 16 + sub]);
            uint2 u2 = __ldg(&uh[(size_t)p2 * 16 + sub]);
            uint2 u3 = __ldg(&uh[(size_t)p3 * 16 + sub]);
            acc4(u0, a0, a1, a2, a3); acc4(u1, a0, a1, a2, a3);
            acc4(u2, a0, a1, a2, a3); acc4(u3, a0, a1, a2, a3);
        }
        for (; j + 2 <= m; j += 2) {
            int p = __shfl_sync(0xffffffffu, sidx, j + half);
            uint2 u = __ldg(&uh[(size_t)p * 16 + sub]);
            acc4(u, a0, a1, a2, a3);
        }
        if (j < m) {
            int p = __shfl_sync(0xffffffffu, sidx, j);
            if (half == 0) {
                uint2 u = __ldg(&uh[(size_t)p * 16 + sub]);
                acc4(u, a0, a1, a2, a3);
            }
        }
    }
    a0 += __shfl_xor_sync(0xffffffffu, a0, 16);
    a1 += __shfl_xor_sync(0xffffffffu, a1, 16);
    a2 += __shfl_xor_sync(0xffffffffu, a2, 16);
    a3 += __shfl_xor_sync(0xffffffffu, a3, 16);
    if (half == 0) red[grp][wg][sub] = make_float4(a0, a1, a2, a3);
    __syncthreads();

    if (t128 < H) {
        const float* r = reinterpret_cast<const float*>(red[grp]);
        float s = r[0 * 64 + t128] + r[1 * 64 + t128]
                + r[2 * 64 + t128] + r[3 * 64 + t128];
        float inv = (deg > 0) ? 1.0f / (float)deg : 0.0f;
        out[node * H + t128] = s * inv + g_yr[node * H + t128];
    }
}

extern "C" void kernel_launch(void* const* d_in, const int* in_sizes, int n_in,
                              void* d_out, int out_size) {
    const float* x   = (const float*)d_in[0];
    const int*   ei  = (const int*)d_in[1];
    const float* W1l = (const float*)d_in[2];
    const float* b1l = (const float*)d_in[3];
    const float* W1r = (const float*)d_in[4];
    const float* W2l = (const float*)d_in[5];
    const float* b2l = (const float*)d_in[6];
    const float* W2r = (const float*)d_in[7];
    float* out = (float*)d_out;

    // CSR build
    k_count <<<(N_EDGES / 4 + 255) / 256, 256>>>(ei);
    k_scan1 <<<SCAN_BLOCKS, 256>>>();
    k_scan23<<<SCAN_BLOCKS, 256>>>();
    k_place <<<(N_EDGES / 4 + 255) / 256, 256>>>(ei);
    // layer 1 aggregation
    k_agg1<<<(N_NODES + 127) / 128, 128>>>(x);
    // fused node transform (layer-1 GEMM + relu + both layer-2 GEMMs)
    k_node<<<(N_NODES + 31) / 32, 256>>>(x, W1l, b1l, W1r, W2l, b2l, W2r);
    // layer-2 aggregation + epilogue
    k_agg2<<<N_NODES / 2, 256>>>(out);
}

// round 9
// speedup vs baseline: 1.0757x; 1.0757x over previous
#include <cuda_runtime.h>
#include <cuda_fp16.h>

#define N_NODES 50000
#define N_EDGES 1600000
#define IN_DIM 6
#define H 64
#define SCAN_BLOCKS ((N_NODES + 255) / 256)   // 196

// Scratch (device globals — zero-initialized at load; no runtime allocation)
__device__ int    g_deg     [N_NODES];        // reset to 0 by k_scan23 each replay
__device__ int    g_rowstart[N_NODES + 1];
__device__ int    g_pos     [N_EDGES];
__device__ int    g_adj     [N_EDGES];
__device__ int    g_bsum    [SCAN_BLOCKS];
__device__ float  g_mean1   [N_NODES * IN_DIM];
__device__ __half g_uh      [N_NODES * H];    // u = z @ W2_l   (fp16, gather operand)
__device__ float  g_yr      [N_NODES * H];    // yr = z @ W2_r + b2_l

// ---- CSR build ----------------------------------------------------------

// 4 edges per thread: vector loads, 4 independent atomic chains
__global__ void k_count(const int* __restrict__ ei) {
    int tid = blockIdx.x * blockDim.x + threadIdx.x;   // N_EDGES/4 threads
    if (tid >= N_EDGES / 4) return;
    const int4* dsts = reinterpret_cast<const int4*>(ei + N_EDGES);
    int4 d = __ldg(&dsts[tid]);
    int p0 = atomicAdd(&g_deg[d.x], 1);
    int p1 = atomicAdd(&g_deg[d.y], 1);
    int p2 = atomicAdd(&g_deg[d.z], 1);
    int p3 = atomicAdd(&g_deg[d.w], 1);
    reinterpret_cast<int4*>(g_pos)[tid] = make_int4(p0, p1, p2, p3);
}

__device__ __forceinline__ int warp_incl_scan(int v, int lane) {
    #pragma unroll
    for (int o = 1; o < 32; o <<= 1) {
        int u = __shfl_up_sync(0xffffffffu, v, o);
        if (lane >= o) v += u;
    }
    return v;
}

// Phase 1: per-block exclusive scan of g_deg -> partial rowstart + block sums
__global__ void k_scan1() {
    __shared__ int ws[8];
    int t = threadIdx.x;
    int i = blockIdx.x * 256 + t;
    int val = (i < N_NODES) ? g_deg[i] : 0;
    int lane = t & 31, w = t >> 5;
    int v = warp_incl_scan(val, lane);
    if (lane == 31) ws[w] = v;
    __syncthreads();
    if (w == 0 && lane < 8) {
        int u = ws[lane];
        #pragma unroll
        for (int o = 1; o < 8; o <<= 1) {
            int p = __shfl_up_sync(0xffu, u, o);
            if (lane >= o) u += p;
        }
        ws[lane] = u;
    }
    __syncthreads();
    int excl = (v - val) + (w > 0 ? ws[w - 1] : 0);
    if (i < N_NODES) g_rowstart[i] = excl;
    if (t == 255) g_bsum[blockIdx.x] = excl + val;
}

// Phase 2+3 merged: every block rescans the 196 block sums locally, derives
// its own offset, applies it, re-arms g_deg, closes the row pointer.
__global__ void k_scan23() {
    __shared__ int ws[8];
    __shared__ int incl[256];
    int t = threadIdx.x;
    int val = (t < SCAN_BLOCKS) ? g_bsum[t] : 0;
    int lane = t & 31, w = t >> 5;
    int v = warp_incl_scan(val, lane);
    if (lane == 31) ws[w] = v;
    __syncthreads();
    if (w == 0 && lane < 8) {
        int u = ws[lane];
        #pragma unroll
        for (int o = 1; o < 8; o <<= 1) {
            int p = __shfl_up_sync(0xffu, u, o);
            if (lane >= o) u += p;
        }
        ws[lane] = u;
    }
    __syncthreads();
    incl[t] = v + (w > 0 ? ws[w - 1] : 0);
    __syncthreads();
    int bid = blockIdx.x;
    int off = (bid > 0) ? incl[bid - 1] : 0;
    int i = bid * 256 + t;
    if (i < N_NODES) {
        g_rowstart[i] += off;
        g_deg[i] = 0;
    }
    if (i == 0) g_rowstart[N_NODES] = N_EDGES;
}

// Atomic-free placement, 4 edges per thread
__global__ void k_place(const int* __restrict__ ei) {
    int tid = blockIdx.x * blockDim.x + threadIdx.x;   // N_EDGES/4 threads
    if (tid >= N_EDGES / 4) return;
    const int4* srcs = reinterpret_cast<const int4*>(ei);
    const int4* dsts = reinterpret_cast<const int4*>(ei + N_EDGES);
    int4 s = __ldg(&srcs[tid]);
    int4 d = __ldg(&dsts[tid]);
    int4 p = reinterpret_cast<const int4*>(g_pos)[tid];
    int r0 = __ldg(&g_rowstart[d.x]);
    int r1 = __ldg(&g_rowstart[d.y]);
    int r2 = __ldg(&g_rowstart[d.z]);
    int r3 = __ldg(&g_rowstart[d.w]);
    g_adj[r0 + p.x] = s.x;
    g_adj[r1 + p.y] = s.y;
    g_adj[r2 + p.z] = s.z;
    g_adj[r3 + p.w] = s.w;
}

// ---- Layer 1 aggregation: warp per node, neighbor-parallel lanes ----------

__global__ void k_agg1(const float* __restrict__ x) {
    int t = threadIdx.x;
    int node = blockIdx.x * 8 + (t >> 5);   // 8 nodes per 256-thread block
    int lane = t & 31;
    if (node >= N_NODES) return;
    int beg = g_rowstart[node], end = g_rowstart[node + 1];

    float a0 = 0, a1 = 0, a2 = 0, a3 = 0, a4 = 0, a5 = 0;
    for (int i = beg + lane; i < end; i += 32) {
        int s = __ldg(&g_adj[i]);
        const float2* xs = reinterpret_cast<const float2*>(x + (size_t)s * IN_DIM);
        float2 p = __ldg(&xs[0]), q = __ldg(&xs[1]), r = __ldg(&xs[2]);
        a0 += p.x; a1 += p.y; a2 += q.x; a3 += q.y; a4 += r.x; a5 += r.y;
    }
    #pragma unroll
    for (int o = 16; o > 0; o >>= 1) {
        a0 += __shfl_xor_sync(0xffffffffu, a0, o);
        a1 += __shfl_xor_sync(0xffffffffu, a1, o);
        a2 += __shfl_xor_sync(0xffffffffu, a2, o);
        a3 += __shfl_xor_sync(0xffffffffu, a3, o);
        a4 += __shfl_xor_sync(0xffffffffu, a4, o);
        a5 += __shfl_xor_sync(0xffffffffu, a5, o);
    }
    if (lane == 0) {
        int deg = end - beg;
        float inv = (deg > 0) ? 1.0f / (float)deg : 0.0f;
        float2* m = reinterpret_cast<float2*>(g_mean1 + (size_t)node * IN_DIM);
        m[0] = make_float2(a0 * inv, a1 * inv);
        m[1] = make_float2(a2 * inv, a3 * inv);
        m[2] = make_float2(a4 * inv, a5 * inv);
    }
}

// ---- Fused node kernel: z = relu(L1), then u = z@W2_l (fp16), yr = z@W2_r + b2_l
__global__ void k_node(const float* __restrict__ x,
                       const float* __restrict__ W1l,
                       const float* __restrict__ b1l,
                       const float* __restrict__ W1r,
                       const float* __restrict__ W2l,
                       const float* __restrict__ b2l,
                       const float* __restrict__ W2r) {
    __shared__ float sW1l[IN_DIM * H];
    __shared__ float sW1r[IN_DIM * H];
    __shared__ float sb1[H];
    __shared__ float sW2l[H * H];
    __shared__ float sW2r[H * H];
    __shared__ float sb2[H];
    __shared__ float sz[32 * H];
    int t = threadIdx.x;
    for (int i = t; i < IN_DIM * H; i += 256) { sW1l[i] = W1l[i]; sW1r[i] = W1r[i]; }
    for (int i = t; i < H * H; i += 256)      { sW2l[i] = W2l[i]; sW2r[i] = W2r[i]; }
    if (t < H) { sb1[t] = b1l[t]; sb2[t] = b2l[t]; }
    __syncthreads();

    int base = blockIdx.x * 32;
    int local = t >> 6;
    int j = t & 63;
    #pragma unroll
    for (int g = 0; g < 8; g++) {
        int node = base + g * 4 + local;
        int ln = g * 4 + local;
        float zv = 0.0f;
        if (node < N_NODES) {
            float acc = sb1[j];
            #pragma unroll
            for (int k = 0; k < IN_DIM; k++) {
                acc += g_mean1[node * IN_DIM + k] * sW1l[k * H + j]
                     + x[node * IN_DIM + k]       * sW1r[k * H + j];
            }
            zv = fmaxf(acc, 0.0f);
        }
        sz[ln * H + j] = zv;
    }
    __syncthreads();
    for (int g = 0; g < 8; g++) {
        int node = base + g * 4 + local;
        if (node < N_NODES) {
            int ln = g * 4 + local;
            float au = 0.0f, ar = sb2[j];
            #pragma unroll 8
            for (int k = 0; k < H; k++) {
                float zv = sz[ln * H + k];
                au += zv * sW2l[k * H + j];
                ar += zv * sW2r[k * H + j];
            }
            g_uh[node * H + j] = __float2half(au);
            g_yr[node * H + j] = ar;
        }
    }
}

// ---- Layer 2 aggregation, fused epilogue: out = mean(u[nbrs]) + yr ---------

__device__ __forceinline__ void acc4(uint2 u, float& a0, float& a1, float& a2, float& a3) {
    __half2 hx = *reinterpret_cast<__half2*>(&u.x);
    __half2 hy = *reinterpret_cast<__half2*>(&u.y);
    float2 fx = __half22float2(hx);
    float2 fy = __half22float2(hy);
    a0 += fx.x; a1 += fx.y; a2 += fy.x; a3 += fy.y;
}

// 2 warps per node (chunk = deg/2 ~ 16): unroll-16 main path actually executes,
// giving 8 independent 8B loads in flight per thread. Block = 4 nodes.
__global__ void k_agg2(float* __restrict__ out) {
    __shared__ float4 red[4][2][16];  // 4 nodes x 2 warps x 64 dims (as float4)
    int t = threadIdx.x;              // 256 = 4 nodes x 2 warps
    int grp  = t >> 6;                // node slot
    int w2   = (t >> 5) & 1;          // warp within node
    int lane = t & 31;
    int half = lane >> 4;             // which neighbor of the pair
    int sub  = lane & 15;             // dim group [sub*4, sub*4+4)
    int node = blockIdx.x * 4 + grp;  // N_NODES % 4 == 0: always valid

    int beg = g_rowstart[node];
    int end = g_rowstart[node + 1];
    int deg = end - beg;
    int chunk = (deg + 1) >> 1;
    int wbeg = beg + w2 * chunk;
    int wend = wbeg + chunk; if (wend > end) wend = end;

    float a0 = 0, a1 = 0, a2 = 0, a3 = 0;
    const uint2* uh = reinterpret_cast<const uint2*>(g_uh);
    for (int base = wbeg; base < wend; base += 32) {
        int idx = base + lane;
        int sidx = (idx < wend) ? __ldg(&g_adj[idx]) : 0;
        int m = wend - base; if (m > 32) m = 32;
        int j = 0;
        for (; j + 16 <= m; j += 16) {
            int p0 = __shfl_sync(0xffffffffu, sidx, j + 0  + half);
            int p1 = __shfl_sync(0xffffffffu, sidx, j + 2  + half);
            int p2 = __shfl_sync(0xffffffffu, sidx, j + 4  + half);
            int p3 = __shfl_sync(0xffffffffu, sidx, j + 6  + half);
            int p4 = __shfl_sync(0xffffffffu, sidx, j + 8  + half);
            int p5 = __shfl_sync(0xffffffffu, sidx, j + 10 + half);
            int p6 = __shfl_sync(0xffffffffu, sidx, j + 12 + half);
            int p7 = __shfl_sync(0xffffffffu, sidx, j + 14 + half);
            uint2 u0 = __ldg(&uh[(size_t)p0 * 16 + sub]);
            uint2 u1 = __ldg(&uh[(size_t)p1 * 16 + sub]);
            uint2 u2 = __ldg(&uh[(size_t)p2 * 16 + sub]);
            uint2 u3 = __ldg(&uh[(size_t)p3 * 16 + sub]);
            uint2 u4 = __ldg(&uh[(size_t)p4 * 16 + sub]);
            uint2 u5 = __ldg(&uh[(size_t)p5 * 16 + sub]);
            uint2 u6 = __ldg(&uh[(size_t)p6 * 16 + sub]);
            uint2 u7 = __ldg(&uh[(size_t)p7 * 16 + sub]);
            acc4(u0, a0, a1, a2, a3); acc4(u1, a0, a1, a2, a3);
            acc4(u2, a0, a1, a2, a3); acc4(u3, a0, a1, a2, a3);
            acc4(u4, a0, a1, a2, a3); acc4(u5, a0, a1, a2, a3);
            acc4(u6, a0, a1, a2, a3); acc4(u7, a0, a1, a2, a3);
        }
        for (; j + 8 <= m; j += 8) {
            int p0 = __shfl_sync(0xffffffffu, sidx, j + 0 + half);
            int p1 = __shfl_sync(0xffffffffu, sidx, j + 2 + half);
            int p2 = __shfl_sync(0xffffffffu, sidx, j + 4 + half);
            int p3 = __shfl_sync(0xffffffffu, sidx, j + 6 + half);
            uint2 u0 = __ldg(&uh[(size_t)p0 * 16 + sub]);
            uint2 u1 = __ldg(&uh[(size_t)p1 * 16 + sub]);
            uint2 u2 = __ldg(&uh[(size_t)p2 * 16 + sub]);
            uint2 u3 = __ldg(&uh[(size_t)p3 * 16 + sub]);
            acc4(u0, a0, a1, a2, a3); acc4(u1, a0, a1, a2, a3);
            acc4(u2, a0, a1, a2, a3); acc4(u3, a0, a1, a2, a3);
        }
        for (; j + 2 <= m; j += 2) {
            int p = __shfl_sync(0xffffffffu, sidx, j + half);
            uint2 u = __ldg(&uh[(size_t)p * 16 + sub]);
            acc4(u, a0, a1, a2, a3);
        }
        if (j < m) {
            int p = __shfl_sync(0xffffffffu, sidx, j);
            if (half == 0) {
                uint2 u = __ldg(&uh[(size_t)p * 16 + sub]);
                acc4(u, a0, a1, a2, a3);
            }
        }
    }
    a0 += __shfl_xor_sync(0xffffffffu, a0, 16);
    a1 += __shfl_xor_sync(0xffffffffu, a1, 16);
    a2 += __shfl_xor_sync(0xffffffffu, a2, 16);
    a3 += __shfl_xor_sync(0xffffffffu, a3, 16);
    if (half == 0) red[grp][w2][sub] = make_float4(a0, a1, a2, a3);
    __syncthreads();

    {
        int n = t >> 6;            // node slot
        int d = t & 63;            // dim
        int nd = blockIdx.x * 4 + n;
        const float* r = reinterpret_cast<const float*>(red[n]);
        float s = r[0 * 64 + d] + r[1 * 64 + d];
        int dg = g_rowstart[nd + 1] - g_rowstart[nd];
        float inv = (dg > 0) ? 1.0f / (float)dg : 0.0f;
        out[nd * H + d] = s * inv + g_yr[nd * H + d];
    }
}

extern "C" void kernel_launch(void* const* d_in, const int* in_sizes, int n_in,
                              void* d_out, int out_size) {
    const float* x   = (const float*)d_in[0];
    const int*   ei  = (const int*)d_in[1];
    const float* W1l = (const float*)d_in[2];
    const float* b1l = (const float*)d_in[3];
    const float* W1r = (const float*)d_in[4];
    const float* W2l = (const float*)d_in[5];
    const float* b2l = (const float*)d_in[6];
    const float* W2r = (const float*)d_in[7];
    float* out = (float*)d_out;

    // CSR build
    k_count <<<(N_EDGES / 4 + 255) / 256, 256>>>(ei);
    k_scan1 <<<SCAN_BLOCKS, 256>>>();
    k_scan23<<<SCAN_BLOCKS, 256>>>();
    k_place <<<(N_EDGES / 4 + 255) / 256, 256>>>(ei);
    // layer 1 aggregation (warp per node)
    k_agg1<<<(N_NODES + 7) / 8, 256>>>(x);
    // fused node transform (layer-1 GEMM + relu + both layer-2 GEMMs)
    k_node<<<(N_NODES + 31) / 32, 256>>>(x, W1l, b1l, W1r, W2l, b2l, W2r);
    // layer-2 aggregation + epilogue (2 warps per node)
    k_agg2<<<N_NODES / 4, 256>>>(out);
}

// round 10
// speedup vs baseline: 1.1138x; 1.0354x over previous
#include <cuda_runtime.h>
#include <cuda_fp16.h>

#define N_NODES 50000
#define N_EDGES 1600000
#define IN_DIM 6
#define H 64
#define SCAN_BLOCKS ((N_NODES + 255) / 256)   // 196

// Scratch (device globals — zero-initialized at load; no runtime allocation)
__device__ int    g_deg     [N_NODES];        // reset to 0 by k_scan23 each replay
__device__ int    g_rowstart[N_NODES + 1];
__device__ int    g_pos     [N_EDGES];
__device__ int    g_adj     [N_EDGES];
__device__ int    g_bsum    [SCAN_BLOCKS];
__device__ __half g_uh      [N_NODES * H];    // u = z @ W2_l   (fp16, gather operand)
__device__ float  g_yr      [N_NODES * H];    // yr = z @ W2_r + b2_l

// ---- CSR build ----------------------------------------------------------

// 4 edges per thread: vector loads, 4 independent atomic chains
__global__ void k_count(const int* __restrict__ ei) {
    int tid = blockIdx.x * blockDim.x + threadIdx.x;   // N_EDGES/4 threads
    if (tid >= N_EDGES / 4) return;
    const int4* dsts = reinterpret_cast<const int4*>(ei + N_EDGES);
    int4 d = __ldg(&dsts[tid]);
    int p0 = atomicAdd(&g_deg[d.x], 1);
    int p1 = atomicAdd(&g_deg[d.y], 1);
    int p2 = atomicAdd(&g_deg[d.z], 1);
    int p3 = atomicAdd(&g_deg[d.w], 1);
    reinterpret_cast<int4*>(g_pos)[tid] = make_int4(p0, p1, p2, p3);
}

__device__ __forceinline__ int warp_incl_scan(int v, int lane) {
    #pragma unroll
    for (int o = 1; o < 32; o <<= 1) {
        int u = __shfl_up_sync(0xffffffffu, v, o);
        if (lane >= o) v += u;
    }
    return v;
}

// Phase 1: per-block exclusive scan of g_deg -> partial rowstart + block sums
__global__ void k_scan1() {
    __shared__ int ws[8];
    int t = threadIdx.x;
    int i = blockIdx.x * 256 + t;
    int val = (i < N_NODES) ? g_deg[i] : 0;
    int lane = t & 31, w = t >> 5;
    int v = warp_incl_scan(val, lane);
    if (lane == 31) ws[w] = v;
    __syncthreads();
    if (w == 0 && lane < 8) {
        int u = ws[lane];
        #pragma unroll
        for (int o = 1; o < 8; o <<= 1) {
            int p = __shfl_up_sync(0xffu, u, o);
            if (lane >= o) u += p;
        }
        ws[lane] = u;
    }
    __syncthreads();
    int excl = (v - val) + (w > 0 ? ws[w - 1] : 0);
    if (i < N_NODES) g_rowstart[i] = excl;
    if (t == 255) g_bsum[blockIdx.x] = excl + val;
}

// Phase 2+3 merged: every block rescans the 196 block sums locally, derives
// its own offset, applies it, re-arms g_deg, closes the row pointer.
__global__ void k_scan23() {
    __shared__ int ws[8];
    __shared__ int incl[256];
    int t = threadIdx.x;
    int val = (t < SCAN_BLOCKS) ? g_bsum[t] : 0;
    int lane = t & 31, w = t >> 5;
    int v = warp_incl_scan(val, lane);
    if (lane == 31) ws[w] = v;
    __syncthreads();
    if (w == 0 && lane < 8) {
        int u = ws[lane];
        #pragma unroll
        for (int o = 1; o < 8; o <<= 1) {
            int p = __shfl_up_sync(0xffu, u, o);
            if (lane >= o) u += p;
        }
        ws[lane] = u;
    }
    __syncthreads();
    incl[t] = v + (w > 0 ? ws[w - 1] : 0);
    __syncthreads();
    int bid = blockIdx.x;
    int off = (bid > 0) ? incl[bid - 1] : 0;
    int i = bid * 256 + t;
    if (i < N_NODES) {
        g_rowstart[i] += off;
        g_deg[i] = 0;
    }
    if (i == 0) g_rowstart[N_NODES] = N_EDGES;
}

// Atomic-free placement, 4 edges per thread
__global__ void k_place(const int* __restrict__ ei) {
    int tid = blockIdx.x * blockDim.x + threadIdx.x;   // N_EDGES/4 threads
    if (tid >= N_EDGES / 4) return;
    const int4* srcs = reinterpret_cast<const int4*>(ei);
    const int4* dsts = reinterpret_cast<const int4*>(ei + N_EDGES);
    int4 s = __ldg(&srcs[tid]);
    int4 d = __ldg(&dsts[tid]);
    int4 p = reinterpret_cast<const int4*>(g_pos)[tid];
    int r0 = __ldg(&g_rowstart[d.x]);
    int r1 = __ldg(&g_rowstart[d.y]);
    int r2 = __ldg(&g_rowstart[d.z]);
    int r3 = __ldg(&g_rowstart[d.w]);
    g_adj[r0 + p.x] = s.x;
    g_adj[r1 + p.y] = s.y;
    g_adj[r2 + p.z] = s.z;
    g_adj[r3 + p.w] = s.w;
}

// ---- Fused node kernel ------------------------------------------------------
// Phase 0: warp-parallel layer-1 mean aggregation (4 nodes per warp) -> smem
// Phase A: z = relu(mean1 @ W1_l + b1_l + x @ W1_r) -> smem
// Phase B: u = z @ W2_l (fp16), yr = z @ W2_r + b2_l -> global
__global__ void k_node(const float* __restrict__ x,
                       const float* __restrict__ W1l,
                       const float* __restrict__ b1l,
                       const float* __restrict__ W1r,
                       const float* __restrict__ W2l,
                       const float* __restrict__ b2l,
                       const float* __restrict__ W2r) {
    __shared__ float sW1l[IN_DIM * H];
    __shared__ float sW1r[IN_DIM * H];
    __shared__ float sb1[H];
    __shared__ float sW2l[H * H];
    __shared__ float sW2r[H * H];
    __shared__ float sb2[H];
    __shared__ float smean[32 * IN_DIM];
    __shared__ float sz[32 * H];
    int t = threadIdx.x;
    for (int i = t; i < IN_DIM * H; i += 256) { sW1l[i] = W1l[i]; sW1r[i] = W1r[i]; }
    for (int i = t; i < H * H; i += 256)      { sW2l[i] = W2l[i]; sW2r[i] = W2r[i]; }
    if (t < H) { sb1[t] = b1l[t]; sb2[t] = b2l[t]; }

    int base = blockIdx.x * 32;
    int w = t >> 5, lane = t & 31;

    // Phase 0: layer-1 aggregation, warp w handles nodes base + w*4 .. +3
    #pragma unroll
    for (int i = 0; i < 4; i++) {
        int node = base + w * 4 + i;
        int ln = w * 4 + i;
        float a0 = 0, a1 = 0, a2 = 0, a3 = 0, a4 = 0, a5 = 0;
        int beg = 0, end = 0;
        if (node < N_NODES) {
            beg = g_rowstart[node];
            end = g_rowstart[node + 1];
            for (int p = beg + lane; p < end; p += 32) {
                int s = __ldg(&g_adj[p]);
                const float2* xs = reinterpret_cast<const float2*>(x + (size_t)s * IN_DIM);
                float2 u = __ldg(&xs[0]), q = __ldg(&xs[1]), r = __ldg(&xs[2]);
                a0 += u.x; a1 += u.y; a2 += q.x; a3 += q.y; a4 += r.x; a5 += r.y;
            }
        }
        #pragma unroll
        for (int o = 16; o > 0; o >>= 1) {
            a0 += __shfl_xor_sync(0xffffffffu, a0, o);
            a1 += __shfl_xor_sync(0xffffffffu, a1, o);
            a2 += __shfl_xor_sync(0xffffffffu, a2, o);
            a3 += __shfl_xor_sync(0xffffffffu, a3, o);
            a4 += __shfl_xor_sync(0xffffffffu, a4, o);
            a5 += __shfl_xor_sync(0xffffffffu, a5, o);
        }
        if (lane == 0 && node < N_NODES) {
            int deg = end - beg;
            float inv = (deg > 0) ? 1.0f / (float)deg : 0.0f;
            smean[ln * IN_DIM + 0] = a0 * inv;
            smean[ln * IN_DIM + 1] = a1 * inv;
            smean[ln * IN_DIM + 2] = a2 * inv;
            smean[ln * IN_DIM + 3] = a3 * inv;
            smean[ln * IN_DIM + 4] = a4 * inv;
            smean[ln * IN_DIM + 5] = a5 * inv;
        }
    }
    __syncthreads();

    int local = t >> 6;
    int j = t & 63;
    // Phase A: z rows into smem
    #pragma unroll
    for (int g = 0; g < 8; g++) {
        int node = base + g * 4 + local;
        int ln = g * 4 + local;
        float zv = 0.0f;
        if (node < N_NODES) {
            float acc = sb1[j];
            #pragma unroll
            for (int k = 0; k < IN_DIM; k++) {
                acc += smean[ln * IN_DIM + k] * sW1l[k * H + j]
                     + x[node * IN_DIM + k]   * sW1r[k * H + j];
            }
            zv = fmaxf(acc, 0.0f);
        }
        sz[ln * H + j] = zv;
    }
    __syncthreads();
    // Phase B: u = z@W2l (fp16), yr = z@W2r + b2l
    for (int g = 0; g < 8; g++) {
        int node = base + g * 4 + local;
        if (node < N_NODES) {
            int ln = g * 4 + local;
            float au = 0.0f, ar = sb2[j];
            #pragma unroll 8
            for (int k = 0; k < H; k++) {
                float zv = sz[ln * H + k];
                au += zv * sW2l[k * H + j];
                ar += zv * sW2r[k * H + j];
            }
            g_uh[node * H + j] = __float2half(au);
            g_yr[node * H + j] = ar;
        }
    }
}

// ---- Layer 2 aggregation, fused epilogue: out = mean(u[nbrs]) + yr ---------

__device__ __forceinline__ void acc4(uint2 u, float& a0, float& a1, float& a2, float& a3) {
    __half2 hx = *reinterpret_cast<__half2*>(&u.x);
    __half2 hy = *reinterpret_cast<__half2*>(&u.y);
    float2 fx = __half22float2(hx);
    float2 fy = __half22float2(hy);
    a0 += fx.x; a1 += fx.y; a2 += fy.x; a3 += fy.y;
}

// 1 warp per node: no smem, no block barrier. Pair-half lanes (half = lane>>4),
// unroll-16 main path = 8 independent 8B loads in flight per thread.
// Final fold = shfl_xor(16); lanes 0-15 write float4 fused with yr.
__global__ void k_agg2(float* __restrict__ out) {
    int t = threadIdx.x;              // 256 = 8 warps = 8 nodes
    int node = blockIdx.x * 8 + (t >> 5);   // N_NODES % 8 == 0
    int lane = t & 31;
    int half = lane >> 4;
    int sub  = lane & 15;

    int beg = g_rowstart[node];
    int end = g_rowstart[node + 1];
    int deg = end - beg;

    float a0 = 0, a1 = 0, a2 = 0, a3 = 0;
    const uint2* uh = reinterpret_cast<const uint2*>(g_uh);
    for (int base = beg; base < end; base += 32) {
        int idx = base + lane;
        int sidx = (idx < end) ? __ldg(&g_adj[idx]) : 0;
        int m = end - base; if (m > 32) m = 32;
        int j = 0;
        for (; j + 16 <= m; j += 16) {
            int p0 = __shfl_sync(0xffffffffu, sidx, j + 0  + half);
            int p1 = __shfl_sync(0xffffffffu, sidx, j + 2  + half);
            int p2 = __shfl_sync(0xffffffffu, sidx, j + 4  + half);
            int p3 = __shfl_sync(0xffffffffu, sidx, j + 6  + half);
            int p4 = __shfl_sync(0xffffffffu, sidx, j + 8  + half);
            int p5 = __shfl_sync(0xffffffffu, sidx, j + 10 + half);
            int p6 = __shfl_sync(0xffffffffu, sidx, j + 12 + half);
            int p7 = __shfl_sync(0xffffffffu, sidx, j + 14 + half);
            uint2 u0 = __ldg(&uh[(size_t)p0 * 16 + sub]);
            uint2 u1 = __ldg(&uh[(size_t)p1 * 16 + sub]);
            uint2 u2 = __ldg(&uh[(size_t)p2 * 16 + sub]);
            uint2 u3 = __ldg(&uh[(size_t)p3 * 16 + sub]);
            uint2 u4 = __ldg(&uh[(size_t)p4 * 16 + sub]);
            uint2 u5 = __ldg(&uh[(size_t)p5 * 16 + sub]);
            uint2 u6 = __ldg(&uh[(size_t)p6 * 16 + sub]);
            uint2 u7 = __ldg(&uh[(size_t)p7 * 16 + sub]);
            acc4(u0, a0, a1, a2, a3); acc4(u1, a0, a1, a2, a3);
            acc4(u2, a0, a1, a2, a3); acc4(u3, a0, a1, a2, a3);
            acc4(u4, a0, a1, a2, a3); acc4(u5, a0, a1, a2, a3);
            acc4(u6, a0, a1, a2, a3); acc4(u7, a0, a1, a2, a3);
        }
        for (; j + 8 <= m; j += 8) {
            int p0 = __shfl_sync(0xffffffffu, sidx, j + 0 + half);
            int p1 = __shfl_sync(0xffffffffu, sidx, j + 2 + half);
            int p2 = __shfl_sync(0xffffffffu, sidx, j + 4 + half);
            int p3 = __shfl_sync(0xffffffffu, sidx, j + 6 + half);
            uint2 u0 = __ldg(&uh[(size_t)p0 * 16 + sub]);
            uint2 u1 = __ldg(&uh[(size_t)p1 * 16 + sub]);
            uint2 u2 = __ldg(&uh[(size_t)p2 * 16 + sub]);
            uint2 u3 = __ldg(&uh[(size_t)p3 * 16 + sub]);
            acc4(u0, a0, a1, a2, a3); acc4(u1, a0, a1, a2, a3);
            acc4(u2, a0, a1, a2, a3); acc4(u3, a0, a1, a2, a3);
        }
        for (; j + 2 <= m; j += 2) {
            int p = __shfl_sync(0xffffffffu, sidx, j + half);
            uint2 u = __ldg(&uh[(size_t)p * 16 + sub]);
            acc4(u, a0, a1, a2, a3);
        }
        if (j < m) {
            int p = __shfl_sync(0xffffffffu, sidx, j);
            if (half == 0) {
                uint2 u = __ldg(&uh[(size_t)p * 16 + sub]);
                acc4(u, a0, a1, a2, a3);
            }
        }
    }
    a0 += __shfl_xor_sync(0xffffffffu, a0, 16);
    a1 += __shfl_xor_sync(0xffffffffu, a1, 16);
    a2 += __shfl_xor_sync(0xffffffffu, a2, 16);
    a3 += __shfl_xor_sync(0xffffffffu, a3, 16);

    if (half == 0) {
        float inv = (deg > 0) ? 1.0f / (float)deg : 0.0f;
        const float4* yr4 = reinterpret_cast<const float4*>(g_yr + (size_t)node * H);
        float4 y = __ldg(&yr4[sub]);
        float4 r = make_float4(a0 * inv + y.x, a1 * inv + y.y,
                               a2 * inv + y.z, a3 * inv + y.w);
        reinterpret_cast<float4*>(out + (size_t)node * H)[sub] = r;
    }
}

extern "C" void kernel_launch(void* const* d_in, const int* in_sizes, int n_in,
                              void* d_out, int out_size) {
    const float* x   = (const float*)d_in[0];
    const int*   ei  = (const int*)d_in[1];
    const float* W1l = (const float*)d_in[2];
    const float* b1l = (const float*)d_in[3];
    const float* W1r = (const float*)d_in[4];
    const float* W2l = (const float*)d_in[5];
    const float* b2l = (const float*)d_in[6];
    const float* W2r = (const float*)d_in[7];
    float* out = (float*)d_out;

    // CSR build
    k_count <<<(N_EDGES / 4 + 255) / 256, 256>>>(ei);
    k_scan1 <<<SCAN_BLOCKS, 256>>>();
    k_scan23<<<SCAN_BLOCKS, 256>>>();
    k_place <<<(N_EDGES / 4 + 255) / 256, 256>>>(ei);
    // fused layer-1 aggregation + node transform (all GEMMs)
    k_node<<<(N_NODES + 31) / 32, 256>>>(x, W1l, b1l, W1r, W2l, b2l, W2r);
    // layer-2 aggregation + epilogue (1 warp per node)
    k_agg2<<<N_NODES / 8, 256>>>(out);
}

// round 11
// speedup vs baseline: 1.1884x; 1.0670x over previous
#include <cuda_runtime.h>
#include <cuda_fp16.h>

#define N_NODES 50000
#define N_EDGES 1600000
#define IN_DIM 6
#define H 64
#define SCAN_BLOCKS ((N_NODES + 255) / 256)   // 196

// Scratch (device globals — zero-initialized at load; no runtime allocation)
__device__ int    g_deg     [N_NODES];        // reset to 0 by k_scan23 each replay
__device__ int    g_rowstart[N_NODES + 1];
__device__ int    g_pos     [N_EDGES];
__device__ int    g_adj     [N_EDGES];
__device__ int    g_bsum    [SCAN_BLOCKS];
__device__ __half g_uh      [N_NODES * H];    // u = z @ W2_l   (fp16, gather operand)
__device__ float  g_yr      [N_NODES * H];    // yr = z @ W2_r + b2_l

// ---- CSR build ----------------------------------------------------------

__global__ void k_count(const int* __restrict__ ei) {
    int tid = blockIdx.x * blockDim.x + threadIdx.x;   // N_EDGES/4 threads
    if (tid >= N_EDGES / 4) return;
    const int4* dsts = reinterpret_cast<const int4*>(ei + N_EDGES);
    int4 d = __ldg(&dsts[tid]);
    int p0 = atomicAdd(&g_deg[d.x], 1);
    int p1 = atomicAdd(&g_deg[d.y], 1);
    int p2 = atomicAdd(&g_deg[d.z], 1);
    int p3 = atomicAdd(&g_deg[d.w], 1);
    reinterpret_cast<int4*>(g_pos)[tid] = make_int4(p0, p1, p2, p3);
}

__device__ __forceinline__ int warp_incl_scan(int v, int lane) {
    #pragma unroll
    for (int o = 1; o < 32; o <<= 1) {
        int u = __shfl_up_sync(0xffffffffu, v, o);
        if (lane >= o) v += u;
    }
    return v;
}

__global__ void k_scan1() {
    __shared__ int ws[8];
    int t = threadIdx.x;
    int i = blockIdx.x * 256 + t;
    int val = (i < N_NODES) ? g_deg[i] : 0;
    int lane = t & 31, w = t >> 5;
    int v = warp_incl_scan(val, lane);
    if (lane == 31) ws[w] = v;
    __syncthreads();
    if (w == 0 && lane < 8) {
        int u = ws[lane];
        #pragma unroll
        for (int o = 1; o < 8; o <<= 1) {
            int p = __shfl_up_sync(0xffu, u, o);
            if (lane >= o) u += p;
        }
        ws[lane] = u;
    }
    __syncthreads();
    int excl = (v - val) + (w > 0 ? ws[w - 1] : 0);
    if (i < N_NODES) g_rowstart[i] = excl;
    if (t == 255) g_bsum[blockIdx.x] = excl + val;
}

__global__ void k_scan23() {
    __shared__ int ws[8];
    __shared__ int incl[256];
    int t = threadIdx.x;
    int val = (t < SCAN_BLOCKS) ? g_bsum[t] : 0;
    int lane = t & 31, w = t >> 5;
    int v = warp_incl_scan(val, lane);
    if (lane == 31) ws[w] = v;
    __syncthreads();
    if (w == 0 && lane < 8) {
        int u = ws[lane];
        #pragma unroll
        for (int o = 1; o < 8; o <<= 1) {
            int p = __shfl_up_sync(0xffu, u, o);
            if (lane >= o) u += p;
        }
        ws[lane] = u;
    }
    __syncthreads();
    incl[t] = v + (w > 0 ? ws[w - 1] : 0);
    __syncthreads();
    int bid = blockIdx.x;
    int off = (bid > 0) ? incl[bid - 1] : 0;
    int i = bid * 256 + t;
    if (i < N_NODES) {
        g_rowstart[i] += off;
        g_deg[i] = 0;
    }
    if (i == 0) g_rowstart[N_NODES] = N_EDGES;
}

__global__ void k_place(const int* __restrict__ ei) {
    int tid = blockIdx.x * blockDim.x + threadIdx.x;   // N_EDGES/4 threads
    if (tid >= N_EDGES / 4) return;
    const int4* srcs = reinterpret_cast<const int4*>(ei);
    const int4* dsts = reinterpret_cast<const int4*>(ei + N_EDGES);
    int4 s = __ldg(&srcs[tid]);
    int4 d = __ldg(&dsts[tid]);
    int4 p = reinterpret_cast<const int4*>(g_pos)[tid];
    int r0 = __ldg(&g_rowstart[d.x]);
    int r1 = __ldg(&g_rowstart[d.y]);
    int r2 = __ldg(&g_rowstart[d.z]);
    int r3 = __ldg(&g_rowstart[d.w]);
    g_adj[r0 + p.x] = s.x;
    g_adj[r1 + p.y] = s.y;
    g_adj[r2 + p.z] = s.z;
    g_adj[r3 + p.w] = s.w;
}

// ---- Fused node kernel ------------------------------------------------------
// Phase 0: warp-parallel layer-1 mean aggregation (4 nodes per warp) -> smem
// Phase A: z = relu(mean1 @ W1_l + b1_l + x @ W1_r) -> smem (float4 per thread)
// Phase B: u = z @ W2_l (fp16), yr = z @ W2_r + b2_l (4 j-columns per thread,
//          LDS.128 weight loads -> 4x fewer shared-mem instructions)
__global__ void k_node(const float* __restrict__ x,
                       const float* __restrict__ W1l,
                       const float* __restrict__ b1l,
                       const float* __restrict__ W1r,
                       const float* __restrict__ W2l,
                       const float* __restrict__ b2l,
                       const float* __restrict__ W2r) {
    __shared__ __align__(16) float sW1l[IN_DIM * H];
    __shared__ __align__(16) float sW1r[IN_DIM * H];
    __shared__ __align__(16) float sb1[H];
    __shared__ __align__(16) float sW2l[H * H];
    __shared__ __align__(16) float sW2r[H * H];
    __shared__ __align__(16) float sb2[H];
    __shared__ __align__(16) float smean[32 * IN_DIM];
    __shared__ __align__(16) float sz[32 * H];
    int t = threadIdx.x;
    for (int i = t; i < IN_DIM * H; i += 256) { sW1l[i] = W1l[i]; sW1r[i] = W1r[i]; }
    for (int i = t; i < H * H; i += 256)      { sW2l[i] = W2l[i]; sW2r[i] = W2r[i]; }
    if (t < H) { sb1[t] = b1l[t]; sb2[t] = b2l[t]; }

    int base = blockIdx.x * 32;
    int w = t >> 5, lane = t & 31;

    // Phase 0: layer-1 aggregation, warp w handles nodes base + w*4 .. +3
    #pragma unroll
    for (int i = 0; i < 4; i++) {
        int node = base + w * 4 + i;
        int ln = w * 4 + i;
        float a0 = 0, a1 = 0, a2 = 0, a3 = 0, a4 = 0, a5 = 0;
        int beg = 0, end = 0;
        if (node < N_NODES) {
            beg = g_rowstart[node];
            end = g_rowstart[node + 1];
            for (int p = beg + lane; p < end; p += 32) {
                int s = __ldg(&g_adj[p]);
                const float2* xs = reinterpret_cast<const float2*>(x + (size_t)s * IN_DIM);
                float2 u = __ldg(&xs[0]), q = __ldg(&xs[1]), r = __ldg(&xs[2]);
                a0 += u.x; a1 += u.y; a2 += q.x; a3 += q.y; a4 += r.x; a5 += r.y;
            }
        }
        #pragma unroll
        for (int o = 16; o > 0; o >>= 1) {
            a0 += __shfl_xor_sync(0xffffffffu, a0, o);
            a1 += __shfl_xor_sync(0xffffffffu, a1, o);
            a2 += __shfl_xor_sync(0xffffffffu, a2, o);
            a3 += __shfl_xor_sync(0xffffffffu, a3, o);
            a4 += __shfl_xor_sync(0xffffffffu, a4, o);
            a5 += __shfl_xor_sync(0xffffffffu, a5, o);
        }
        if (lane == 0 && node < N_NODES) {
            int deg = end - beg;
            float inv = (deg > 0) ? 1.0f / (float)deg : 0.0f;
            smean[ln * IN_DIM + 0] = a0 * inv;
            smean[ln * IN_DIM + 1] = a1 * inv;
            smean[ln * IN_DIM + 2] = a2 * inv;
            smean[ln * IN_DIM + 3] = a3 * inv;
            smean[ln * IN_DIM + 4] = a4 * inv;
            smean[ln * IN_DIM + 5] = a5 * inv;
        }
    }
    __syncthreads();

    // Thread remap: nslot (16 node slots) x j4 (16 column quads)
    int nslot = t >> 4;
    int j4 = t & 15;
    int j0 = j4 * 4;

    #pragma unroll
    for (int p = 0; p < 2; p++) {
        int ln = p * 16 + nslot;
        int node = base + ln;
        // Phase A: z quad
        float4 z4 = make_float4(0.f, 0.f, 0.f, 0.f);
        if (node < N_NODES) {
            float4 acc = *reinterpret_cast<const float4*>(&sb1[j0]);
            #pragma unroll
            for (int k = 0; k < IN_DIM; k++) {
                float mk = smean[ln * IN_DIM + k];
                float xk = __ldg(&x[(size_t)node * IN_DIM + k]);
                float4 wl = *reinterpret_cast<const float4*>(&sW1l[k * H + j0]);
                float4 wr = *reinterpret_cast<const float4*>(&sW1r[k * H + j0]);
                acc.x += mk * wl.x + xk * wr.x;
                acc.y += mk * wl.y + xk * wr.y;
                acc.z += mk * wl.z + xk * wr.z;
                acc.w += mk * wl.w + xk * wr.w;
            }
            z4 = make_float4(fmaxf(acc.x, 0.f), fmaxf(acc.y, 0.f),
                             fmaxf(acc.z, 0.f), fmaxf(acc.w, 0.f));
        }
        *reinterpret_cast<float4*>(&sz[ln * H + j0]) = z4;
        __syncwarp();   // sz row ln produced & consumed within this warp

        // Phase B: u / yr quads
        if (node < N_NODES) {
            float4 au = make_float4(0.f, 0.f, 0.f, 0.f);
            float4 ar = *reinterpret_cast<const float4*>(&sb2[j0]);
            #pragma unroll 8
            for (int k = 0; k < H; k++) {
                float zv = sz[ln * H + k];
                float4 wl = *reinterpret_cast<const float4*>(&sW2l[k * H + j0]);
                float4 wr = *reinterpret_cast<const float4*>(&sW2r[k * H + j0]);
                au.x += zv * wl.x; au.y += zv * wl.y;
                au.z += zv * wl.z; au.w += zv * wl.w;
                ar.x += zv * wr.x; ar.y += zv * wr.y;
                ar.z += zv * wr.z; ar.w += zv * wr.w;
            }
            __half2 h01 = __floats2half2_rn(au.x, au.y);
            __half2 h23 = __floats2half2_rn(au.z, au.w);
            uint2 us;
            us.x = *reinterpret_cast<unsigned*>(&h01);
            us.y = *reinterpret_cast<unsigned*>(&h23);
            reinterpret_cast<uint2*>(g_uh)[(size_t)node * 16 + j4] = us;
            reinterpret_cast<float4*>(g_yr)[(size_t)node * 16 + j4] = ar;
        }
    }
}

// ---- Layer 2 aggregation, fused epilogue: out = mean(u[nbrs]) + yr ---------

__device__ __forceinline__ void acc4(uint2 u, float& a0, float& a1, float& a2, float& a3) {
    __half2 hx = *reinterpret_cast<__half2*>(&u.x);
    __half2 hy = *reinterpret_cast<__half2*>(&u.y);
    float2 fx = __half22float2(hx);
    float2 fy = __half22float2(hy);
    a0 += fx.x; a1 += fx.y; a2 += fy.x; a3 += fy.y;
}

// 1 warp per node: no smem, no block barrier. Pair-half lanes (half = lane>>4),
// unroll-16 main path = 8 independent 8B loads in flight per thread.
__global__ void k_agg2(float* __restrict__ out) {
    int t = threadIdx.x;              // 256 = 8 warps = 8 nodes
    int node = blockIdx.x * 8 + (t >> 5);   // N_NODES % 8 == 0
    int lane = t & 31;
    int half = lane >> 4;
    int sub  = lane & 15;

    int beg = g_rowstart[node];
    int end = g_rowstart[node + 1];
    int deg = end - beg;

    float a0 = 0, a1 = 0, a2 = 0, a3 = 0;
    const uint2* uh = reinterpret_cast<const uint2*>(g_uh);
    for (int base = beg; base < end; base += 32) {
        int idx = base + lane;
        int sidx = (idx < end) ? __ldg(&g_adj[idx]) : 0;
        int m = end - base; if (m > 32) m = 32;
        int j = 0;
        for (; j + 16 <= m; j += 16) {
            int p0 = __shfl_sync(0xffffffffu, sidx, j + 0  + half);
            int p1 = __shfl_sync(0xffffffffu, sidx, j + 2  + half);
            int p2 = __shfl_sync(0xffffffffu, sidx, j + 4  + half);
            int p3 = __shfl_sync(0xffffffffu, sidx, j + 6  + half);
            int p4 = __shfl_sync(0xffffffffu, sidx, j + 8  + half);
            int p5 = __shfl_sync(0xffffffffu, sidx, j + 10 + half);
            int p6 = __shfl_sync(0xffffffffu, sidx, j + 12 + half);
            int p7 = __shfl_sync(0xffffffffu, sidx, j + 14 + half);
            uint2 u0 = __ldg(&uh[(size_t)p0 * 16 + sub]);
            uint2 u1 = __ldg(&uh[(size_t)p1 * 16 + sub]);
            uint2 u2 = __ldg(&uh[(size_t)p2 * 16 + sub]);
            uint2 u3 = __ldg(&uh[(size_t)p3 * 16 + sub]);
            uint2 u4 = __ldg(&uh[(size_t)p4 * 16 + sub]);
            uint2 u5 = __ldg(&uh[(size_t)p5 * 16 + sub]);
            uint2 u6 = __ldg(&uh[(size_t)p6 * 16 + sub]);
            uint2 u7 = __ldg(&uh[(size_t)p7 * 16 + sub]);
            acc4(u0, a0, a1, a2, a3); acc4(u1, a0, a1, a2, a3);
            acc4(u2, a0, a1, a2, a3); acc4(u3, a0, a1, a2, a3);
            acc4(u4, a0, a1, a2, a3); acc4(u5, a0, a1, a2, a3);
            acc4(u6, a0, a1, a2, a3); acc4(u7, a0, a1, a2, a3);
        }
        for (; j + 8 <= m; j += 8) {
            int p0 = __shfl_sync(0xffffffffu, sidx, j + 0 + half);
            int p1 = __shfl_sync(0xffffffffu, sidx, j + 2 + half);
            int p2 = __shfl_sync(0xffffffffu, sidx, j + 4 + half);
            int p3 = __shfl_sync(0xffffffffu, sidx, j + 6 + half);
            uint2 u0 = __ldg(&uh[(size_t)p0 * 16 + sub]);
            uint2 u1 = __ldg(&uh[(size_t)p1 * 16 + sub]);
            uint2 u2 = __ldg(&uh[(size_t)p2 * 16 + sub]);
            uint2 u3 = __ldg(&uh[(size_t)p3 * 16 + sub]);
            acc4(u0, a0, a1, a2, a3); acc4(u1, a0, a1, a2, a3);
            acc4(u2, a0, a1, a2, a3); acc4(u3, a0, a1, a2, a3);
        }
        for (; j + 2 <= m; j += 2) {
            int p = __shfl_sync(0xffffffffu, sidx, j + half);
            uint2 u = __ldg(&uh[(size_t)p * 16 + sub]);
            acc4(u, a0, a1, a2, a3);
        }
        if (j < m) {
            int p = __shfl_sync(0xffffffffu, sidx, j);
            if (half == 0) {
                uint2 u = __ldg(&uh[(size_t)p * 16 + sub]);
                acc4(u, a0, a1, a2, a3);
            }
        }
    }
    a0 += __shfl_xor_sync(0xffffffffu, a0, 16);
    a1 += __shfl_xor_sync(0xffffffffu, a1, 16);
    a2 += __shfl_xor_sync(0xffffffffu, a2, 16);
    a3 += __shfl_xor_sync(0xffffffffu, a3, 16);

    if (half == 0) {
        float inv = (deg > 0) ? 1.0f / (float)deg : 0.0f;
        const float4* yr4 = reinterpret_cast<const float4*>(g_yr + (size_t)node * H);
        float4 y = __ldg(&yr4[sub]);
        float4 r = make_float4(a0 * inv + y.x, a1 * inv + y.y,
                               a2 * inv + y.z, a3 * inv + y.w);
        reinterpret_cast<float4*>(out + (size_t)node * H)[sub] = r;
    }
}

extern "C" void kernel_launch(void* const* d_in, const int* in_sizes, int n_in,
                              void* d_out, int out_size) {
    const float* x   = (const float*)d_in[0];
    const int*   ei  = (const int*)d_in[1];
    const float* W1l = (const float*)d_in[2];
    const float* b1l = (const float*)d_in[3];
    const float* W1r = (const float*)d_in[4];
    const float* W2l = (const float*)d_in[5];
    const float* b2l = (const float*)d_in[6];
    const float* W2r = (const float*)d_in[7];
    float* out = (float*)d_out;

    // CSR build
    k_count <<<(N_EDGES / 4 + 255) / 256, 256>>>(ei);
    k_scan1 <<<SCAN_BLOCKS, 256>>>();
    k_scan23<<<SCAN_BLOCKS, 256>>>();
    k_place <<<(N_EDGES / 4 + 255) / 256, 256>>>(ei);
    // fused layer-1 aggregation + node transform (all GEMMs, LDS.128 weights)
    k_node<<<(N_NODES + 31) / 32, 256>>>(x, W1l, b1l, W1r, W2l, b2l, W2r);
    // layer-2 aggregation + epilogue (1 warp per node)
    k_agg2<<<N_NODES / 8, 256>>>(out);
}

// round 12
// speedup vs baseline: 1.4014x; 1.1792x over previous
#include <cuda_runtime.h>
#include <cuda_fp16.h>

#define N_NODES 50000
#define N_EDGES 1600000
#define IN_DIM 6
#define H 64
#define SCAN_BLOCKS ((N_NODES + 255) / 256)   // 196

// Scratch (device globals — zero-initialized at load; no runtime allocation)
__device__ int    g_deg     [N_NODES];        // reset to 0 by k_scan23 each replay
__device__ int    g_rowstart[N_NODES + 1];
__device__ int    g_pos     [N_EDGES];
__device__ int    g_adj     [N_EDGES];
__device__ int    g_bsum    [SCAN_BLOCKS];
__device__ __half g_uh      [N_NODES * H];    // u = z @ W2_l   (fp16, gather operand)
__device__ float  g_yr      [N_NODES * H];    // yr = z @ W2_r + b2_l

// ---- CSR build ----------------------------------------------------------

__global__ void k_count(const int* __restrict__ ei) {
    int tid = blockIdx.x * blockDim.x + threadIdx.x;   // N_EDGES/4 threads
    if (tid >= N_EDGES / 4) return;
    const int4* dsts = reinterpret_cast<const int4*>(ei + N_EDGES);
    int4 d = __ldg(&dsts[tid]);
    int p0 = atomicAdd(&g_deg[d.x], 1);
    int p1 = atomicAdd(&g_deg[d.y], 1);
    int p2 = atomicAdd(&g_deg[d.z], 1);
    int p3 = atomicAdd(&g_deg[d.w], 1);
    reinterpret_cast<int4*>(g_pos)[tid] = make_int4(p0, p1, p2, p3);
}

__device__ __forceinline__ int warp_incl_scan(int v, int lane) {
    #pragma unroll
    for (int o = 1; o < 32; o <<= 1) {
        int u = __shfl_up_sync(0xffffffffu, v, o);
        if (lane >= o) v += u;
    }
    return v;
}

__global__ void k_scan1() {
    __shared__ int ws[8];
    int t = threadIdx.x;
    int i = blockIdx.x * 256 + t;
    int val = (i < N_NODES) ? g_deg[i] : 0;
    int lane = t & 31, w = t >> 5;
    int v = warp_incl_scan(val, lane);
    if (lane == 31) ws[w] = v;
    __syncthreads();
    if (w == 0 && lane < 8) {
        int u = ws[lane];
        #pragma unroll
        for (int o = 1; o < 8; o <<= 1) {
            int p = __shfl_up_sync(0xffu, u, o);
            if (lane >= o) u += p;
        }
        ws[lane] = u;
    }
    __syncthreads();
    int excl = (v - val) + (w > 0 ? ws[w - 1] : 0);
    if (i < N_NODES) g_rowstart[i] = excl;
    if (t == 255) g_bsum[blockIdx.x] = excl + val;
}

__global__ void k_scan23() {
    __shared__ int ws[8];
    __shared__ int incl[256];
    int t = threadIdx.x;
    int val = (t < SCAN_BLOCKS) ? g_bsum[t] : 0;
    int lane = t & 31, w = t >> 5;
    int v = warp_incl_scan(val, lane);
    if (lane == 31) ws[w] = v;
    __syncthreads();
    if (w == 0 && lane < 8) {
        int u = ws[lane];
        #pragma unroll
        for (int o = 1; o < 8; o <<= 1) {
            int p = __shfl_up_sync(0xffu, u, o);
            if (lane >= o) u += p;
        }
        ws[lane] = u;
    }
    __syncthreads();
    incl[t] = v + (w > 0 ? ws[w - 1] : 0);
    __syncthreads();
    int bid = blockIdx.x;
    int off = (bid > 0) ? incl[bid - 1] : 0;
    int i = bid * 256 + t;
    if (i < N_NODES) {
        g_rowstart[i] += off;
        g_deg[i] = 0;
    }
    if (i == 0) g_rowstart[N_NODES] = N_EDGES;
}

__global__ void k_place(const int* __restrict__ ei) {
    int tid = blockIdx.x * blockDim.x + threadIdx.x;   // N_EDGES/4 threads
    if (tid >= N_EDGES / 4) return;
    const int4* srcs = reinterpret_cast<const int4*>(ei);
    const int4* dsts = reinterpret_cast<const int4*>(ei + N_EDGES);
    int4 s = __ldg(&srcs[tid]);
    int4 d = __ldg(&dsts[tid]);
    int4 p = reinterpret_cast<const int4*>(g_pos)[tid];
    int r0 = __ldg(&g_rowstart[d.x]);
    int r1 = __ldg(&g_rowstart[d.y]);
    int r2 = __ldg(&g_rowstart[d.z]);
    int r3 = __ldg(&g_rowstart[d.w]);
    g_adj[r0 + p.x] = s.x;
    g_adj[r1 + p.y] = s.y;
    g_adj[r2 + p.z] = s.z;
    g_adj[r3 + p.w] = s.w;
}

// ---- Fused node kernel ------------------------------------------------------
// Phase 0: warp-parallel layer-1 mean aggregation (4 nodes per warp) -> smem
// Phase A: z = relu(mean1 @ W1_l + b1_l + x @ W1_r) -> smem, 2 nodes/thread
// Phase B: u = z@W2_l (fp16), yr = z@W2_r + b2_l; 2 nodes x 4 cols per thread
//          (register blocking: each LDS.128 weight quad feeds 2 nodes)
__global__ void k_node(const float* __restrict__ x,
                       const float* __restrict__ W1l,
                       const float* __restrict__ b1l,
                       const float* __restrict__ W1r,
                       const float* __restrict__ W2l,
                       const float* __restrict__ b2l,
                       const float* __restrict__ W2r) {
    __shared__ __align__(16) float sW1l[IN_DIM * H];
    __shared__ __align__(16) float sW1r[IN_DIM * H];
    __shared__ __align__(16) float sb1[H];
    __shared__ __align__(16) float sW2l[H * H];
    __shared__ __align__(16) float sW2r[H * H];
    __shared__ __align__(16) float sb2[H];
    __shared__ __align__(16) float smean[32 * IN_DIM];
    __shared__ __align__(16) float sz[32 * H];
    int t = threadIdx.x;
    for (int i = t; i < IN_DIM * H; i += 256) { sW1l[i] = W1l[i]; sW1r[i] = W1r[i]; }
    for (int i = t; i < H * H; i += 256)      { sW2l[i] = W2l[i]; sW2r[i] = W2r[i]; }
    if (t < H) { sb1[t] = b1l[t]; sb2[t] = b2l[t]; }

    int base = blockIdx.x * 32;
    int w = t >> 5, lane = t & 31;

    // Phase 0: layer-1 aggregation, warp w handles nodes base + w*4 .. +3
    #pragma unroll
    for (int i = 0; i < 4; i++) {
        int node = base + w * 4 + i;
        int ln = w * 4 + i;
        float a0 = 0, a1 = 0, a2 = 0, a3 = 0, a4 = 0, a5 = 0;
        int beg = 0, end = 0;
        if (node < N_NODES) {
            beg = g_rowstart[node];
            end = g_rowstart[node + 1];
            for (int p = beg + lane; p < end; p += 32) {
                int s = __ldg(&g_adj[p]);
                const float2* xs = reinterpret_cast<const float2*>(x + (size_t)s * IN_DIM);
                float2 u = __ldg(&xs[0]), q = __ldg(&xs[1]), r = __ldg(&xs[2]);
                a0 += u.x; a1 += u.y; a2 += q.x; a3 += q.y; a4 += r.x; a5 += r.y;
            }
        }
        #pragma unroll
        for (int o = 16; o > 0; o >>= 1) {
            a0 += __shfl_xor_sync(0xffffffffu, a0, o);
            a1 += __shfl_xor_sync(0xffffffffu, a1, o);
            a2 += __shfl_xor_sync(0xffffffffu, a2, o);
            a3 += __shfl_xor_sync(0xffffffffu, a3, o);
            a4 += __shfl_xor_sync(0xffffffffu, a4, o);
            a5 += __shfl_xor_sync(0xffffffffu, a5, o);
        }
        if (lane == 0 && node < N_NODES) {
            int deg = end - beg;
            float inv = (deg > 0) ? 1.0f / (float)deg : 0.0f;
            smean[ln * IN_DIM + 0] = a0 * inv;
            smean[ln * IN_DIM + 1] = a1 * inv;
            smean[ln * IN_DIM + 2] = a2 * inv;
            smean[ln * IN_DIM + 3] = a3 * inv;
            smean[ln * IN_DIM + 4] = a4 * inv;
            smean[ln * IN_DIM + 5] = a5 * inv;
        }
    }
    __syncthreads();   // weights + smean visible to all

    // Thread remap: np (16 node-pairs) x j4 (16 column quads)
    // Warp w covers np in {2w, 2w+1} -> rows 4w..4w+3: same warp that
    // aggregated them (phase 0) and that will consume sz (phase B).
    int np = t >> 4;
    int j4 = t & 15;
    int j0 = j4 * 4;
    int ln0 = np * 2, ln1 = np * 2 + 1;
    int node0 = base + ln0, node1 = base + ln1;

    // Phase A: z quads for both nodes of the pair
    {
        float4 acc0 = *reinterpret_cast<const float4*>(&sb1[j0]);
        float4 acc1 = acc0;
        #pragma unroll
        for (int k = 0; k < IN_DIM; k++) {
            float4 wl = *reinterpret_cast<const float4*>(&sW1l[k * H + j0]);
            float4 wr = *reinterpret_cast<const float4*>(&sW1r[k * H + j0]);
            float m0 = smean[ln0 * IN_DIM + k];
            float m1 = smean[ln1 * IN_DIM + k];
            float x0 = (node0 < N_NODES) ? __ldg(&x[(size_t)node0 * IN_DIM + k]) : 0.0f;
            float x1 = (node1 < N_NODES) ? __ldg(&x[(size_t)node1 * IN_DIM + k]) : 0.0f;
            acc0.x += m0 * wl.x + x0 * wr.x;  acc0.y += m0 * wl.y + x0 * wr.y;
            acc0.z += m0 * wl.z + x0 * wr.z;  acc0.w += m0 * wl.w + x0 * wr.w;
            acc1.x += m1 * wl.x + x1 * wr.x;  acc1.y += m1 * wl.y + x1 * wr.y;
            acc1.z += m1 * wl.z + x1 * wr.z;  acc1.w += m1 * wl.w + x1 * wr.w;
        }
        float4 z0 = make_float4(fmaxf(acc0.x, 0.f), fmaxf(acc0.y, 0.f),
                                fmaxf(acc0.z, 0.f), fmaxf(acc0.w, 0.f));
        float4 z1 = make_float4(fmaxf(acc1.x, 0.f), fmaxf(acc1.y, 0.f),
                                fmaxf(acc1.z, 0.f), fmaxf(acc1.w, 0.f));
        *reinterpret_cast<float4*>(&sz[ln0 * H + j0]) = z0;
        *reinterpret_cast<float4*>(&sz[ln1 * H + j0]) = z1;
    }
    __syncwarp();   // sz rows 4w..4w+3 produced & consumed within warp w

    // Phase B: u / yr quads for both nodes; each weight quad feeds 2 nodes
    {
        float4 au0 = make_float4(0.f, 0.f, 0.f, 0.f);
        float4 au1 = au0;
        float4 ar0 = *reinterpret_cast<const float4*>(&sb2[j0]);
        float4 ar1 = ar0;
        #pragma unroll 8
        for (int k = 0; k < H; k++) {
            float4 wl = *reinterpret_cast<const float4*>(&sW2l[k * H + j0]);
            float4 wr = *reinterpret_cast<const float4*>(&sW2r[k * H + j0]);
            float z0 = sz[ln0 * H + k];
            float z1 = sz[ln1 * H + k];
            au0.x += z0 * wl.x; au0.y += z0 * wl.y; au0.z += z0 * wl.z; au0.w += z0 * wl.w;
            ar0.x += z0 * wr.x; ar0.y += z0 * wr.y; ar0.z += z0 * wr.z; ar0.w += z0 * wr.w;
            au1.x += z1 * wl.x; au1.y += z1 * wl.y; au1.z += z1 * wl.z; au1.w += z1 * wl.w;
            ar1.x += z1 * wr.x; ar1.y += z1 * wr.y; ar1.z += z1 * wr.z; ar1.w += z1 * wr.w;
        }
        if (node0 < N_NODES) {
            __half2 h01 = __floats2half2_rn(au0.x, au0.y);
            __half2 h23 = __floats2half2_rn(au0.z, au0.w);
            uint2 us;
            us.x = *reinterpret_cast<unsigned*>(&h01);
            us.y = *reinterpret_cast<unsigned*>(&h23);
            reinterpret_cast<uint2*>(g_uh)[(size_t)node0 * 16 + j4] = us;
            reinterpret_cast<float4*>(g_yr)[(size_t)node0 * 16 + j4] = ar0;
        }
        if (node1 < N_NODES) {
            __half2 h01 = __floats2half2_rn(au1.x, au1.y);
            __half2 h23 = __floats2half2_rn(au1.z, au1.w);
            uint2 us;
            us.x = *reinterpret_cast<unsigned*>(&h01);
            us.y = *reinterpret_cast<unsigned*>(&h23);
            reinterpret_cast<uint2*>(g_uh)[(size_t)node1 * 16 + j4] = us;
            reinterpret_cast<float4*>(g_yr)[(size_t)node1 * 16 + j4] = ar1;
        }
    }
}

// ---- Layer 2 aggregation, fused epilogue: out = mean(u[nbrs]) + yr ---------

__device__ __forceinline__ void acc4(uint2 u, float& a0, float& a1, float& a2, float& a3) {
    __half2 hx = *reinterpret_cast<__half2*>(&u.x);
    __half2 hy = *reinterpret_cast<__half2*>(&u.y);
    float2 fx = __half22float2(hx);
    float2 fy = __half22float2(hy);
    a0 += fx.x; a1 += fx.y; a2 += fy.x; a3 += fy.y;
}

// 1 warp per node: no smem, no block barrier. Pair-half lanes (half = lane>>4),
// unroll-16 main path = 8 independent 8B loads in flight per thread.
__global__ void k_agg2(float* __restrict__ out) {
    int t = threadIdx.x;              // 256 = 8 warps = 8 nodes
    int node = blockIdx.x * 8 + (t >> 5);   // N_NODES % 8 == 0
    int lane = t & 31;
    int half = lane >> 4;
    int sub  = lane & 15;

    int beg = g_rowstart[node];
    int end = g_rowstart[node + 1];
    int deg = end - beg;

    float a0 = 0, a1 = 0, a2 = 0, a3 = 0;
    const uint2* uh = reinterpret_cast<const uint2*>(g_uh);
    for (int base = beg; base < end; base += 32) {
        int idx = base + lane;
        int sidx = (idx < end) ? __ldg(&g_adj[idx]) : 0;
        int m = end - base; if (m > 32) m = 32;
        int j = 0;
        for (; j + 16 <= m; j += 16) {
            int p0 = __shfl_sync(0xffffffffu, sidx, j + 0  + half);
            int p1 = __shfl_sync(0xffffffffu, sidx, j + 2  + half);
            int p2 = __shfl_sync(0xffffffffu, sidx, j + 4  + half);
            int p3 = __shfl_sync(0xffffffffu, sidx, j + 6  + half);
            int p4 = __shfl_sync(0xffffffffu, sidx, j + 8  + half);
            int p5 = __shfl_sync(0xffffffffu, sidx, j + 10 + half);
            int p6 = __shfl_sync(0xffffffffu, sidx, j + 12 + half);
            int p7 = __shfl_sync(0xffffffffu, sidx, j + 14 + half);
            uint2 u0 = __ldg(&uh[(size_t)p0 * 16 + sub]);
            uint2 u1 = __ldg(&uh[(size_t)p1 * 16 + sub]);
            uint2 u2 = __ldg(&uh[(size_t)p2 * 16 + sub]);
            uint2 u3 = __ldg(&uh[(size_t)p3 * 16 + sub]);
            uint2 u4 = __ldg(&uh[(size_t)p4 * 16 + sub]);
            uint2 u5 = __ldg(&uh[(size_t)p5 * 16 + sub]);
            uint2 u6 = __ldg(&uh[(size_t)p6 * 16 + sub]);
            uint2 u7 = __ldg(&uh[(size_t)p7 * 16 + sub]);
            acc4(u0, a0, a1, a2, a3); acc4(u1, a0, a1, a2, a3);
            acc4(u2, a0, a1, a2, a3); acc4(u3, a0, a1, a2, a3);
            acc4(u4, a0, a1, a2, a3); acc4(u5, a0, a1, a2, a3);
            acc4(u6, a0, a1, a2, a3); acc4(u7, a0, a1, a2, a3);
        }
        for (; j + 8 <= m; j += 8) {
            int p0 = __shfl_sync(0xffffffffu, sidx, j + 0 + half);
            int p1 = __shfl_sync(0xffffffffu, sidx, j + 2 + half);
            int p2 = __shfl_sync(0xffffffffu, sidx, j + 4 + half);
            int p3 = __shfl_sync(0xffffffffu, sidx, j + 6 + half);
            uint2 u0 = __ldg(&uh[(size_t)p0 * 16 + sub]);
            uint2 u1 = __ldg(&uh[(size_t)p1 * 16 + sub]);
            uint2 u2 = __ldg(&uh[(size_t)p2 * 16 + sub]);
            uint2 u3 = __ldg(&uh[(size_t)p3 * 16 + sub]);
            acc4(u0, a0, a1, a2, a3); acc4(u1, a0, a1, a2, a3);
            acc4(u2, a0, a1, a2, a3); acc4(u3, a0, a1, a2, a3);
        }
        for (; j + 2 <= m; j += 2) {
            int p = __shfl_sync(0xffffffffu, sidx, j + half);
            uint2 u = __ldg(&uh[(size_t)p * 16 + sub]);
            acc4(u, a0, a1, a2, a3);
        }
        if (j < m) {
            int p = __shfl_sync(0xffffffffu, sidx, j);
            if (half == 0) {
                uint2 u = __ldg(&uh[(size_t)p * 16 + sub]);
                acc4(u, a0, a1, a2, a3);
            }
        }
    }
    a0 += __shfl_xor_sync(0xffffffffu, a0, 16);
    a1 += __shfl_xor_sync(0xffffffffu, a1, 16);
    a2 += __shfl_xor_sync(0xffffffffu, a2, 16);
    a3 += __shfl_xor_sync(0xffffffffu, a3, 16);

    if (half == 0) {
        float inv = (deg > 0) ? 1.0f / (float)deg : 0.0f;
        const float4* yr4 = reinterpret_cast<const float4*>(g_yr + (size_t)node * H);
        float4 y = __ldg(&yr4[sub]);
        float4 r = make_float4(a0 * inv + y.x, a1 * inv + y.y,
                               a2 * inv + y.z, a3 * inv + y.w);
        reinterpret_cast<float4*>(out + (size_t)node * H)[sub] = r;
    }
}

extern "C" void kernel_launch(void* const* d_in, const int* in_sizes, int n_in,
                              void* d_out, int out_size) {
    const float* x   = (const float*)d_in[0];
    const int*   ei  = (const int*)d_in[1];
    const float* W1l = (const float*)d_in[2];
    const float* b1l = (const float*)d_in[3];
    const float* W1r = (const float*)d_in[4];
    const float* W2l = (const float*)d_in[5];
    const float* b2l = (const float*)d_in[6];
    const float* W2r = (const float*)d_in[7];
    float* out = (float*)d_out;

    // CSR build
    k_count <<<(N_EDGES / 4 + 255) / 256, 256>>>(ei);
    k_scan1 <<<SCAN_BLOCKS, 256>>>();
    k_scan23<<<SCAN_BLOCKS, 256>>>();
    k_place <<<(N_EDGES / 4 + 255) / 256, 256>>>(ei);
    // fused layer-1 aggregation + node transform (register-blocked GEMMs)
    k_node<<<(N_NODES + 31) / 32, 256>>>(x, W1l, b1l, W1r, W2l, b2l, W2r);
    // layer-2 aggregation + epilogue (1 warp per node)
    k_agg2<<<N_NODES / 8, 256>>>(out);
}

// round 13
// speedup vs baseline: 1.5119x; 1.0789x over previous
#include <cuda_runtime.h>
#include <cuda_fp16.h>

#define N_NODES 50000
#define N_EDGES 1600000
#define IN_DIM 6
#define H 64
#define SCAN_BLOCKS ((N_NODES + 255) / 256)   // 196
#define NB 64                                  // nodes per k_node block

// Scratch (device globals — zero-initialized at load; no runtime allocation)
__device__ int    g_deg     [N_NODES];        // reset to 0 by k_scan23 each replay
__device__ int    g_rowstart[N_NODES + 1];
__device__ int    g_pos     [N_EDGES];
__device__ int    g_adj     [N_EDGES];
__device__ int    g_bsum    [SCAN_BLOCKS];
__device__ __half g_uh      [N_NODES * H];    // u = z @ W2_l   (fp16, gather operand)
__device__ float  g_yr      [N_NODES * H];    // yr = z @ W2_r + b2_l

// ---- CSR build ----------------------------------------------------------

__global__ void k_count(const int* __restrict__ ei) {
    int tid = blockIdx.x * blockDim.x + threadIdx.x;   // N_EDGES/4 threads
    if (tid >= N_EDGES / 4) return;
    const int4* dsts = reinterpret_cast<const int4*>(ei + N_EDGES);
    int4 d = __ldg(&dsts[tid]);
    int p0 = atomicAdd(&g_deg[d.x], 1);
    int p1 = atomicAdd(&g_deg[d.y], 1);
    int p2 = atomicAdd(&g_deg[d.z], 1);
    int p3 = atomicAdd(&g_deg[d.w], 1);
    reinterpret_cast<int4*>(g_pos)[tid] = make_int4(p0, p1, p2, p3);
}

__device__ __forceinline__ int warp_incl_scan(int v, int lane) {
    #pragma unroll
    for (int o = 1; o < 32; o <<= 1) {
        int u = __shfl_up_sync(0xffffffffu, v, o);
        if (lane >= o) v += u;
    }
    return v;
}

__global__ void k_scan1() {
    __shared__ int ws[8];
    int t = threadIdx.x;
    int i = blockIdx.x * 256 + t;
    int val = (i < N_NODES) ? g_deg[i] : 0;
    int lane = t & 31, w = t >> 5;
    int v = warp_incl_scan(val, lane);
    if (lane == 31) ws[w] = v;
    __syncthreads();
    if (w == 0 && lane < 8) {
        int u = ws[lane];
        #pragma unroll
        for (int o = 1; o < 8; o <<= 1) {
            int p = __shfl_up_sync(0xffu, u, o);
            if (lane >= o) u += p;
        }
        ws[lane] = u;
    }
    __syncthreads();
    int excl = (v - val) + (w > 0 ? ws[w - 1] : 0);
    if (i < N_NODES) g_rowstart[i] = excl;
    if (t == 255) g_bsum[blockIdx.x] = excl + val;
}

__global__ void k_scan23() {
    __shared__ int ws[8];
    __shared__ int incl[256];
    int t = threadIdx.x;
    int val = (t < SCAN_BLOCKS) ? g_bsum[t] : 0;
    int lane = t & 31, w = t >> 5;
    int v = warp_incl_scan(val, lane);
    if (lane == 31) ws[w] = v;
    __syncthreads();
    if (w == 0 && lane < 8) {
        int u = ws[lane];
        #pragma unroll
        for (int o = 1; o < 8; o <<= 1) {
            int p = __shfl_up_sync(0xffu, u, o);
            if (lane >= o) u += p;
        }
        ws[lane] = u;
    }
    __syncthreads();
    incl[t] = v + (w > 0 ? ws[w - 1] : 0);
    __syncthreads();
    int bid = blockIdx.x;
    int off = (bid > 0) ? incl[bid - 1] : 0;
    int i = bid * 256 + t;
    if (i < N_NODES) {
        g_rowstart[i] += off;
        g_deg[i] = 0;
    }
    if (i == 0) g_rowstart[N_NODES] = N_EDGES;
}

__global__ void k_place(const int* __restrict__ ei) {
    int tid = blockIdx.x * blockDim.x + threadIdx.x;   // N_EDGES/4 threads
    if (tid >= N_EDGES / 4) return;
    const int4* srcs = reinterpret_cast<const int4*>(ei);
    const int4* dsts = reinterpret_cast<const int4*>(ei + N_EDGES);
    int4 s = __ldg(&srcs[tid]);
    int4 d = __ldg(&dsts[tid]);
    int4 p = reinterpret_cast<const int4*>(g_pos)[tid];
    int r0 = __ldg(&g_rowstart[d.x]);
    int r1 = __ldg(&g_rowstart[d.y]);
    int r2 = __ldg(&g_rowstart[d.z]);
    int r3 = __ldg(&g_rowstart[d.w]);
    g_adj[r0 + p.x] = s.x;
    g_adj[r1 + p.y] = s.y;
    g_adj[r2 + p.z] = s.z;
    g_adj[r3 + p.w] = s.w;
}

// ---- Fused node kernel ------------------------------------------------------
// 64 nodes per block. Phase 0: warp w aggregates nodes 8w..8w+7 (layer-1 mean).
// Phase A: z = relu(mean1 @ W1_l + b1_l + x @ W1_r), 4 nodes/thread -> smem.
// Phase B: u = z@W2_l (fp16), yr = z@W2_r + b2_l; 4 nodes x 4 cols per thread
//          (each LDS.128 weight quad feeds 4 nodes = 32 FMA-outputs).
__global__ void k_node(const float* __restrict__ x,
                       const float* __restrict__ W1l,
                       const float* __restrict__ b1l,
                       const float* __restrict__ W1r,
                       const float* __restrict__ W2l,
                       const float* __restrict__ b2l,
                       const float* __restrict__ W2r) {
    __shared__ __align__(16) float sW1l[IN_DIM * H];
    __shared__ __align__(16) float sW1r[IN_DIM * H];
    __shared__ __align__(16) float sb1[H];
    __shared__ __align__(16) float sW2l[H * H];
    __shared__ __align__(16) float sW2r[H * H];
    __shared__ __align__(16) float sb2[H];
    __shared__ __align__(16) float smean[NB * IN_DIM];
    __shared__ __align__(16) float sz[NB * H];
    int t = threadIdx.x;
    for (int i = t; i < IN_DIM * H; i += 256) { sW1l[i] = W1l[i]; sW1r[i] = W1r[i]; }
    for (int i = t; i < H * H; i += 256)      { sW2l[i] = W2l[i]; sW2r[i] = W2r[i]; }
    if (t < H) { sb1[t] = b1l[t]; sb2[t] = b2l[t]; }

    int base = blockIdx.x * NB;
    int w = t >> 5, lane = t & 31;

    // Phase 0: layer-1 aggregation, warp w handles nodes base + w*8 .. +7
    #pragma unroll
    for (int i = 0; i < 8; i++) {
        int node = base + w * 8 + i;
        int ln = w * 8 + i;
        float a0 = 0, a1 = 0, a2 = 0, a3 = 0, a4 = 0, a5 = 0;
        int beg = 0, end = 0;
        if (node < N_NODES) {
            beg = g_rowstart[node];
            end = g_rowstart[node + 1];
            for (int p = beg + lane; p < end; p += 32) {
                int s = __ldg(&g_adj[p]);
                const float2* xs = reinterpret_cast<const float2*>(x + (size_t)s * IN_DIM);
                float2 u = __ldg(&xs[0]), q = __ldg(&xs[1]), r = __ldg(&xs[2]);
                a0 += u.x; a1 += u.y; a2 += q.x; a3 += q.y; a4 += r.x; a5 += r.y;
            }
        }
        #pragma unroll
        for (int o = 16; o > 0; o >>= 1) {
            a0 += __shfl_xor_sync(0xffffffffu, a0, o);
            a1 += __shfl_xor_sync(0xffffffffu, a1, o);
            a2 += __shfl_xor_sync(0xffffffffu, a2, o);
            a3 += __shfl_xor_sync(0xffffffffu, a3, o);
            a4 += __shfl_xor_sync(0xffffffffu, a4, o);
            a5 += __shfl_xor_sync(0xffffffffu, a5, o);
        }
        if (lane == 0 && node < N_NODES) {
            int deg = end - beg;
            float inv = (deg > 0) ? 1.0f / (float)deg : 0.0f;
            smean[ln * IN_DIM + 0] = a0 * inv;
            smean[ln * IN_DIM + 1] = a1 * inv;
            smean[ln * IN_DIM + 2] = a2 * inv;
            smean[ln * IN_DIM + 3] = a3 * inv;
            smean[ln * IN_DIM + 4] = a4 * inv;
            smean[ln * IN_DIM + 5] = a5 * inv;
        }
    }
    __syncthreads();   // weights + smean visible to all

    // Thread remap: nq (16 node-quads) x j4 (16 column quads).
    // Warp w covers nq in {2w, 2w+1} -> rows 8w..8w+7: same rows warp w
    // aggregated in phase 0 and consumes in phase B -> __syncwarp suffices.
    int nq = t >> 4;
    int j4 = t & 15;
    int j0 = j4 * 4;
    int lnb = nq * 4;             // first of 4 node rows for this thread
    int nodeb = base + lnb;

    // Phase A: z quads for 4 nodes
    {
        float4 acc[4];
        float4 b = *reinterpret_cast<const float4*>(&sb1[j0]);
        #pragma unroll
        for (int i = 0; i < 4; i++) acc[i] = b;
        #pragma unroll
        for (int k = 0; k < IN_DIM; k++) {
            float4 wl = *reinterpret_cast<const float4*>(&sW1l[k * H + j0]);
            float4 wr = *reinterpret_cast<const float4*>(&sW1r[k * H + j0]);
            #pragma unroll
            for (int i = 0; i < 4; i++) {
                int node = nodeb + i;
                float m = smean[(lnb + i) * IN_DIM + k];
                float xv = (node < N_NODES) ? __ldg(&x[(size_t)node * IN_DIM + k]) : 0.0f;
                acc[i].x += m * wl.x + xv * wr.x;
                acc[i].y += m * wl.y + xv * wr.y;
                acc[i].z += m * wl.z + xv * wr.z;
                acc[i].w += m * wl.w + xv * wr.w;
            }
        }
        #pragma unroll
        for (int i = 0; i < 4; i++) {
            float4 z = make_float4(fmaxf(acc[i].x, 0.f), fmaxf(acc[i].y, 0.f),
                                   fmaxf(acc[i].z, 0.f), fmaxf(acc[i].w, 0.f));
            *reinterpret_cast<float4*>(&sz[(lnb + i) * H + j0]) = z;
        }
    }
    __syncwarp();   // sz rows 8w..8w+7 produced & consumed within warp w

    // Phase B: u / yr quads for 4 nodes; each weight quad feeds 4 nodes
    {
        float4 au[4], ar[4];
        float4 b2 = *reinterpret_cast<const float4*>(&sb2[j0]);
        #pragma unroll
        for (int i = 0; i < 4; i++) {
            au[i] = make_float4(0.f, 0.f, 0.f, 0.f);
            ar[i] = b2;
        }
        #pragma unroll 4
        for (int k = 0; k < H; k++) {
            float4 wl = *reinterpret_cast<const float4*>(&sW2l[k * H + j0]);
            float4 wr = *reinterpret_cast<const float4*>(&sW2r[k * H + j0]);
            #pragma unroll
            for (int i = 0; i < 4; i++) {
                float zv = sz[(lnb + i) * H + k];
                au[i].x += zv * wl.x; au[i].y += zv * wl.y;
                au[i].z += zv * wl.z; au[i].w += zv * wl.w;
                ar[i].x += zv * wr.x; ar[i].y += zv * wr.y;
                ar[i].z += zv * wr.z; ar[i].w += zv * wr.w;
            }
        }
        #pragma unroll
        for (int i = 0; i < 4; i++) {
            int node = nodeb + i;
            if (node < N_NODES) {
                __half2 h01 = __floats2half2_rn(au[i].x, au[i].y);
                __half2 h23 = __floats2half2_rn(au[i].z, au[i].w);
                uint2 us;
                us.x = *reinterpret_cast<unsigned*>(&h01);
                us.y = *reinterpret_cast<unsigned*>(&h23);
                reinterpret_cast<uint2*>(g_uh)[(size_t)node * 16 + j4] = us;
                reinterpret_cast<float4*>(g_yr)[(size_t)node * 16 + j4] = ar[i];
            }
        }
    }
}

// ---- Layer 2 aggregation, fused epilogue: out = mean(u[nbrs]) + yr ---------

__device__ __forceinline__ void acc4(uint2 u, float& a0, float& a1, float& a2, float& a3) {
    __half2 hx = *reinterpret_cast<__half2*>(&u.x);
    __half2 hy = *reinterpret_cast<__half2*>(&u.y);
    float2 fx = __half22float2(hx);
    float2 fy = __half22float2(hy);
    a0 += fx.x; a1 += fx.y; a2 += fy.x; a3 += fy.y;
}

// 1 warp per node: no smem, no block barrier. Pair-half lanes (half = lane>>4),
// unroll-16 main path = 8 independent 8B loads in flight per thread.
__global__ void k_agg2(float* __restrict__ out) {
    int t = threadIdx.x;              // 256 = 8 warps = 8 nodes
    int node = blockIdx.x * 8 + (t >> 5);   // N_NODES % 8 == 0
    int lane = t & 31;
    int half = lane >> 4;
    int sub  = lane & 15;

    int beg = g_rowstart[node];
    int end = g_rowstart[node + 1];
    int deg = end - beg;

    float a0 = 0, a1 = 0, a2 = 0, a3 = 0;
    const uint2* uh = reinterpret_cast<const uint2*>(g_uh);
    for (int base = beg; base < end; base += 32) {
        int idx = base + lane;
        int sidx = (idx < end) ? __ldg(&g_adj[idx]) : 0;
        int m = end - base; if (m > 32) m = 32;
        int j = 0;
        for (; j + 16 <= m; j += 16) {
            int p0 = __shfl_sync(0xffffffffu, sidx, j + 0  + half);
            int p1 = __shfl_sync(0xffffffffu, sidx, j + 2  + half);
            int p2 = __shfl_sync(0xffffffffu, sidx, j + 4  + half);
            int p3 = __shfl_sync(0xffffffffu, sidx, j + 6  + half);
            int p4 = __shfl_sync(0xffffffffu, sidx, j + 8  + half);
            int p5 = __shfl_sync(0xffffffffu, sidx, j + 10 + half);
            int p6 = __shfl_sync(0xffffffffu, sidx, j + 12 + half);
            int p7 = __shfl_sync(0xffffffffu, sidx, j + 14 + half);
            uint2 u0 = __ldg(&uh[(size_t)p0 * 16 + sub]);
            uint2 u1 = __ldg(&uh[(size_t)p1 * 16 + sub]);
            uint2 u2 = __ldg(&uh[(size_t)p2 * 16 + sub]);
            uint2 u3 = __ldg(&uh[(size_t)p3 * 16 + sub]);
            uint2 u4 = __ldg(&uh[(size_t)p4 * 16 + sub]);
            uint2 u5 = __ldg(&uh[(size_t)p5 * 16 + sub]);
            uint2 u6 = __ldg(&uh[(size_t)p6 * 16 + sub]);
            uint2 u7 = __ldg(&uh[(size_t)p7 * 16 + sub]);
            acc4(u0, a0, a1, a2, a3); acc4(u1, a0, a1, a2, a3);
            acc4(u2, a0, a1, a2, a3); acc4(u3, a0, a1, a2, a3);
            acc4(u4, a0, a1, a2, a3); acc4(u5, a0, a1, a2, a3);
            acc4(u6, a0, a1, a2, a3); acc4(u7, a0, a1, a2, a3);
        }
        for (; j + 8 <= m; j += 8) {
            int p0 = __shfl_sync(0xffffffffu, sidx, j + 0 + half);
            int p1 = __shfl_sync(0xffffffffu, sidx, j + 2 + half);
            int p2 = __shfl_sync(0xffffffffu, sidx, j + 4 + half);
            int p3 = __shfl_sync(0xffffffffu, sidx, j + 6 + half);
            uint2 u0 = __ldg(&uh[(size_t)p0 * 16 + sub]);
            uint2 u1 = __ldg(&uh[(size_t)p1 * 16 + sub]);
            uint2 u2 = __ldg(&uh[(size_t)p2 * 16 + sub]);
            uint2 u3 = __ldg(&uh[(size_t)p3 * 16 + sub]);
            acc4(u0, a0, a1, a2, a3); acc4(u1, a0, a1, a2, a3);
            acc4(u2, a0, a1, a2, a3); acc4(u3, a0, a1, a2, a3);
        }
        for (; j + 2 <= m; j += 2) {
            int p = __shfl_sync(0xffffffffu, sidx, j + half);
            uint2 u = __ldg(&uh[(size_t)p * 16 + sub]);
            acc4(u, a0, a1, a2, a3);
        }
        if (j < m) {
            int p = __shfl_sync(0xffffffffu, sidx, j);
            if (half == 0) {
                uint2 u = __ldg(&uh[(size_t)p * 16 + sub]);
                acc4(u, a0, a1, a2, a3);
            }
        }
    }
    a0 += __shfl_xor_sync(0xffffffffu, a0, 16);
    a1 += __shfl_xor_sync(0xffffffffu, a1, 16);
    a2 += __shfl_xor_sync(0xffffffffu, a2, 16);
    a3 += __shfl_xor_sync(0xffffffffu, a3, 16);

    if (half == 0) {
        float inv = (deg > 0) ? 1.0f / (float)deg : 0.0f;
        const float4* yr4 = reinterpret_cast<const float4*>(g_yr + (size_t)node * H);
        float4 y = __ldg(&yr4[sub]);
        float4 r = make_float4(a0 * inv + y.x, a1 * inv + y.y,
                               a2 * inv + y.z, a3 * inv + y.w);
        reinterpret_cast<float4*>(out + (size_t)node * H)[sub] = r;
    }
}

extern "C" void kernel_launch(void* const* d_in, const int* in_sizes, int n_in,
                              void* d_out, int out_size) {
    const float* x   = (const float*)d_in[0];
    const int*   ei  = (const int*)d_in[1];
    const float* W1l = (const float*)d_in[2];
    const float* b1l = (const float*)d_in[3];
    const float* W1r = (const float*)d_in[4];
    const float* W2l = (const float*)d_in[5];
    const float* b2l = (const float*)d_in[6];
    const float* W2r = (const float*)d_in[7];
    float* out = (float*)d_out;

    // CSR build
    k_count <<<(N_EDGES / 4 + 255) / 256, 256>>>(ei);
    k_scan1 <<<SCAN_BLOCKS, 256>>>();
    k_scan23<<<SCAN_BLOCKS, 256>>>();
    k_place <<<(N_EDGES / 4 + 255) / 256, 256>>>(ei);
    // fused layer-1 aggregation + node transform (4-node register blocking)
    k_node<<<(N_NODES + NB - 1) / NB, 256>>>(x, W1l, b1l, W1r, W2l, b2l, W2r);
    // layer-2 aggregation + epilogue (1 warp per node)
    k_agg2<<<N_NODES / 8, 256>>>(out);
}